// round 8
// baseline (speedup 1.0000x reference)
#include <cuda_runtime.h>
#include <cuda_fp16.h>
#include <math.h>
#include <stdint.h>

#define N_NODES 10000
#define N_EDGES 120000
#define E_TOT   130000
#define F_IN    66
#define HEADS   10
#define FHEAD   66
#define D1      660
#define D2      1320
#define D3      1000
#define D4      64
#define M_PAD   10112        // 79 * 128

#define KP_X    96
#define KP_AGG  704
#define KP_H2   1344
#define KP_H3   1024
#define NP_GAT  768
#define NP_GCN  1408
#define NP_G1   1024
#define NP_G2   128
#define XTS     672          // fp16 row stride for xt / h1

// ---------------- scratch ------------------------------------------------------
__device__             float g_as [N_NODES * HEADS];
__device__             float g_ad [N_NODES * HEADS];
__device__             float g_dinv[N_NODES];
__device__ __align__(16) float g_h4a[N_NODES * D4];
__device__ __align__(16) float g_h4b[N_NODES * D4];

__device__ __align__(16) __half g_xth [N_NODES * XTS];
__device__ __align__(16) __half g_h1h [N_NODES * XTS];

// ---------------- CSR over destination ------------------------------------------
__device__ int g_deg_i [N_NODES];
__device__ int g_fill  [N_NODES];
__device__ int g_rowptr[N_NODES + 1];
__device__ int g_csr_src[E_TOT];

// ---------------- fp16 GEMM buffers ----------------------------------------------
__device__ __align__(16) __half g_axh [M_PAD * KP_X];
__device__ __align__(16) __half g_aah [M_PAD * KP_AGG];
__device__ __align__(16) __half g_a2h [M_PAD * KP_H2];
__device__ __align__(16) __half g_a3h [M_PAD * KP_H3];
__device__ __align__(16) __half g_bgat[NP_GAT * KP_X];
__device__ __align__(16) __half g_bgcn[NP_GCN * KP_AGG];
__device__ __align__(16) __half g_bg1 [NP_G1 * KP_H2];
__device__ __align__(16) __half g_bg2 [NP_G2 * KP_H3];

// ---------------- baseline-PTX helpers -------------------------------------------
__device__ __forceinline__ uint32_t smem_u32(const void* p) {
    uint32_t a;
    asm("{ .reg .u64 t; cvta.to.shared.u64 t, %1; cvt.u32.u64 %0, t; }" : "=r"(a) : "l"(p));
    return a;
}
__device__ __forceinline__ void cp16(uint32_t dst, const void* src) {
    asm volatile("cp.async.cg.shared.global [%0], [%1], 16;" :: "r"(dst), "l"(src));
}
__device__ __forceinline__ void cp_commit() { asm volatile("cp.async.commit_group;"); }
template<int N> __device__ __forceinline__ void cp_wait() {
    asm volatile("cp.async.wait_group %0;" :: "n"(N));
}
__device__ __forceinline__ void ldsm4(uint32_t* r, uint32_t addr) {
    asm volatile("ldmatrix.sync.aligned.m8n8.x4.shared.b16 {%0,%1,%2,%3}, [%4];"
        : "=r"(r[0]), "=r"(r[1]), "=r"(r[2]), "=r"(r[3]) : "r"(addr));
}
__device__ __forceinline__ void mma_f16(float* d, const uint32_t* a, const uint32_t* b) {
    asm volatile("mma.sync.aligned.m16n8k16.row.col.f32.f16.f16.f32 "
        "{%0,%1,%2,%3}, {%4,%5,%6,%7}, {%8,%9}, {%0,%1,%2,%3};"
        : "+f"(d[0]), "+f"(d[1]), "+f"(d[2]), "+f"(d[3])
        : "r"(a[0]), "r"(a[1]), "r"(a[2]), "r"(a[3]), "r"(b[0]), "r"(b[1]));
}

// ---------------- misc ------------------------------------------------------------
__device__ __forceinline__ void edge_sd(const int* ei, int e, int& s, int& d) {
    if (e < N_EDGES) { s = ei[e]; d = ei[N_EDGES + e]; }
    else             { s = d = e - N_EDGES; }
}
__device__ __forceinline__ float leaky(float v, float sl) { return v >= 0.f ? v : sl * v; }

// ---------------- CSR build ---------------------------------------------------------
__global__ void zero_small_kernel() {
    int i = blockIdx.x * blockDim.x + threadIdx.x;
    if (i < N_NODES) { g_deg_i[i] = 0; g_fill[i] = 0; }
}
__global__ void deg_kernel(const int* __restrict__ ei) {
    int e = blockIdx.x * blockDim.x + threadIdx.x;
    if (e >= E_TOT) return;
    int s, d; edge_sd(ei, e, s, d);
    atomicAdd(&g_deg_i[d], 1);
}
__global__ void scan_kernel() {   // single block; also computes dinv
    __shared__ int sm[1024];
    int tid = threadIdx.x;
    int base = tid * 10;
    int local[10]; int sum = 0;
    #pragma unroll
    for (int i = 0; i < 10; i++) {
        int v = (base + i < N_NODES) ? g_deg_i[base + i] : 0;
        if (base + i < N_NODES) g_dinv[base + i] = rsqrtf(fmaxf((float)v, 1.f));
        local[i] = sum; sum += v;
    }
    sm[tid] = sum; __syncthreads();
    for (int off = 1; off < 1024; off <<= 1) {
        int v = (tid >= off) ? sm[tid - off] : 0;
        __syncthreads();
        sm[tid] += v;
        __syncthreads();
    }
    int pre = (tid > 0) ? sm[tid - 1] : 0;
    #pragma unroll
    for (int i = 0; i < 10; i++)
        if (base + i < N_NODES) g_rowptr[base + i] = pre + local[i];
    if (tid == 1023) g_rowptr[N_NODES] = sm[1023];
}
__global__ void fill_kernel(const int* __restrict__ ei) {
    int e = blockIdx.x * blockDim.x + threadIdx.x;
    if (e >= E_TOT) return;
    int s, d; edge_sd(ei, e, s, d);
    int pos = atomicAdd(&g_fill[d], 1);
    g_csr_src[g_rowptr[d] + pos] = s;
}

// ---------------- fused converts (one launch for all 5 regions) -----------------------
#define R0 (NP_GAT * KP_X)
#define R1 (NP_GCN * KP_AGG)
#define R2 (NP_G1 * KP_H2)
#define R3 (NP_G2 * KP_H3)
#define R4 (M_PAD * KP_X)
#define CVT_TOTAL (R0 + R1 + R2 + R3 + R4)

__device__ __forceinline__ void cvtB_one(const float* W, __half* dst, int idx,
                                         int K, int Nn, int Kp) {
    int n = idx / Kp, k = idx - n * Kp;
    float v = (k < K && n < Nn) ? W[(long)k * Nn + n] : 0.f;
    dst[idx] = __float2half_rn(v);
}
__global__ void cvt_all_kernel(const float* __restrict__ x,
                               const float* __restrict__ Wgat, const float* __restrict__ Wgcn,
                               const float* __restrict__ Wg1,  const float* __restrict__ Wg2) {
    int idx = blockIdx.x * blockDim.x + threadIdx.x;
    if (idx >= CVT_TOTAL) return;
    if (idx < R0) { cvtB_one(Wgat, g_bgat, idx, F_IN, D1, KP_X); return; }
    idx -= R0;
    if (idx < R1) { cvtB_one(Wgcn, g_bgcn, idx, D1, D2, KP_AGG); return; }
    idx -= R1;
    if (idx < R2) { cvtB_one(Wg1, g_bg1, idx, D2, D3, KP_H2); return; }
    idx -= R2;
    if (idx < R3) { cvtB_one(Wg2, g_bg2, idx, D3, D4, KP_H3); return; }
    idx -= R3;
    {   // cvtA: x -> g_axh
        int r = idx / KP_X, c = idx - r * KP_X;
        float v = (r < N_NODES && c < F_IN) ? x[(long)r * F_IN + c] : 0.f;
        g_axh[idx] = __float2half_rn(v);
    }
}

// ---------------- HMMA GEMM (single fp16, 4-stage cp.async, optional split-K) ---------
#define TSTRIDE  80
#define B_HI_OFF 10240
#define STAGE_SZ 20480
#define GEMM_SMEM (4 * STAGE_SZ)

__device__ __forceinline__ void fill_stage(uint32_t st,
        const __half* __restrict__ A, const __half* __restrict__ B,
        int m0, int n0, int Kp, int k0, int tid) {
    #pragma unroll
    for (int i = 0; i < 2; i++) {
        int lin = tid + i * 256;
        int r = lin >> 2, cc = lin & 3;
        uint32_t d = st + r * TSTRIDE + cc * 16;
        cp16(d,            (const char*)(A + (long)(m0 + r) * Kp + k0) + cc * 16);
        cp16(d + B_HI_OFF, (const char*)(B + (long)(n0 + r) * Kp + k0) + cc * 16);
    }
    cp_commit();
}

template<bool BIAS, bool ACT, bool SPLIT>
__global__ __launch_bounds__(256, 1)
void mma_gemm(const __half* __restrict__ Ah, const __half* __restrict__ Bh,
              const float* __restrict__ bias, float* __restrict__ C,
              float* __restrict__ C2, __half* __restrict__ Sh,
              int Kp, int chunks, int Nreal, int ldC) {
    extern __shared__ char smem[];
    const uint32_t tile0 = smem_u32(smem);
    const int tid = threadIdx.x, wid = tid >> 5, lane = tid & 31;
    const int m0 = blockIdx.y * 128, n0 = blockIdx.x * 128;
    const int kbase = blockIdx.z * chunks * 32;   // split-K offset
    const int mwoff = (wid >> 1) * 32, nwoff = (wid & 1) * 64;

    const int mat = lane >> 3, mrow = lane & 7;
    uint32_t a_off[2], b_off[4];
    #pragma unroll
    for (int ti = 0; ti < 2; ti++)
        a_off[ti] = (uint32_t)((mwoff + ti * 16 + ((mat & 1) << 3) + mrow) * TSTRIDE
                               + (mat >> 1) * 16);
    #pragma unroll
    for (int nt = 0; nt < 4; nt++)
        b_off[nt] = (uint32_t)((nwoff + nt * 16 + ((mat >> 1) << 3) + mrow) * TSTRIDE
                               + (mat & 1) * 16);

    float acc[2][8][4] = {};

    fill_stage(tile0, Ah, Bh, m0, n0, Kp, kbase, tid);
    if (chunks > 1) fill_stage(tile0 + STAGE_SZ, Ah, Bh, m0, n0, Kp, kbase + 32, tid);
    if (chunks > 2) fill_stage(tile0 + 2 * STAGE_SZ, Ah, Bh, m0, n0, Kp, kbase + 64, tid);

    for (int c = 0; c < chunks; c++) {
        if (c + 2 < chunks)      cp_wait<2>();
        else if (c + 1 < chunks) cp_wait<1>();
        else                     cp_wait<0>();
        __syncthreads();
        if (c + 3 < chunks)
            fill_stage(tile0 + ((c + 3) & 3) * STAGE_SZ, Ah, Bh,
                       m0, n0, Kp, kbase + (c + 3) * 32, tid);
        uint32_t sb = tile0 + (c & 3) * STAGE_SZ;
        #pragma unroll
        for (int kh = 0; kh < 2; kh++) {
            uint32_t ah[2][4], bh[4][4];
            #pragma unroll
            for (int ti = 0; ti < 2; ti++)
                ldsm4(ah[ti], sb + a_off[ti] + kh * 32);
            #pragma unroll
            for (int nt = 0; nt < 4; nt++)
                ldsm4(bh[nt], sb + B_HI_OFF + b_off[nt] + kh * 32);
            #pragma unroll
            for (int ti = 0; ti < 2; ti++)
                #pragma unroll
                for (int nt = 0; nt < 8; nt++)
                    mma_f16(acc[ti][nt], ah[ti], &bh[nt >> 1][(nt & 1) * 2]);
        }
    }

    float* Cout = (blockIdx.z == 0) ? C : C2;
    const int lr = lane >> 2, lc = (lane & 3) * 2;
    #pragma unroll
    for (int ti = 0; ti < 2; ti++)
        #pragma unroll
        for (int rp = 0; rp < 2; rp++) {
            int gr = m0 + mwoff + ti * 16 + rp * 8 + lr;
            if (gr >= N_NODES) continue;
            if (!SPLIT) {
                float* crow = Cout + (long)gr * ldC;
                #pragma unroll
                for (int nt = 0; nt < 8; nt++) {
                    int gc = n0 + nwoff + nt * 8 + lc;
                    float v0 = acc[ti][nt][rp * 2 + 0];
                    float v1 = acc[ti][nt][rp * 2 + 1];
                    if (gc < Nreal) {
                        if (BIAS) v0 += bias[gc];
                        if (ACT)  v0 = leaky(v0, 0.01f);
                        crow[gc] = v0;
                    }
                    if (gc + 1 < Nreal) {
                        if (BIAS) v1 += bias[gc + 1];
                        if (ACT)  v1 = leaky(v1, 0.01f);
                        crow[gc + 1] = v1;
                    }
                }
            } else {
                __half* hr = Sh + (long)gr * ldC;
                #pragma unroll
                for (int nt = 0; nt < 8; nt++) {
                    int gc = n0 + nwoff + nt * 8 + lc;
                    if (gc >= ldC) continue;
                    float v0 = 0.f, v1 = 0.f;
                    if (gc < Nreal) {
                        v0 = acc[ti][nt][rp * 2 + 0];
                        if (BIAS) v0 += bias[gc];
                        if (ACT)  v0 = leaky(v0, 0.01f);
                    }
                    if (gc + 1 < Nreal) {
                        v1 = acc[ti][nt][rp * 2 + 1];
                        if (BIAS) v1 += bias[gc + 1];
                        if (ACT)  v1 = leaky(v1, 0.01f);
                    }
                    __half2 hp;
                    hp.x = __float2half_rn(v0);
                    hp.y = __float2half_rn(v1);
                    *(__half2*)(hr + gc) = hp;
                }
            }
        }
}

// ---------------- attention coefficients (fp16 xt) -----------------------------
__global__ void attn_kernel(const float* __restrict__ att_src,
                            const float* __restrict__ att_dst) {
    int idx = blockIdx.x * blockDim.x + threadIdx.x;
    if (idx >= N_NODES * HEADS) return;
    int n = idx / HEADS, h = idx % HEADS;
    const __half* xr = g_xth + (long)n * XTS + h * FHEAD;
    const float* as = att_src + h * FHEAD;
    const float* ad = att_dst + h * FHEAD;
    float s = 0.f, d = 0.f;
    #pragma unroll
    for (int f = 0; f < FHEAD; f++) {
        float v = __half2float(xr[f]);
        s += v * as[f]; d += v * ad[f];
    }
    g_as[idx] = s; g_ad[idx] = d;
}

// ---------------- GAT gather (fp16 features, warp per dst node) -----------------
__global__ void gat_gather_kernel(const float* __restrict__ b_gat) {
    int gw = (blockIdx.x * blockDim.x + threadIdx.x) >> 5;
    int lane = threadIdx.x & 31;
    int wl = threadIdx.x >> 5;
    __shared__ float sal[8][12];
    if (gw >= N_NODES) return;
    int beg = g_rowptr[gw], end = g_rowptr[gw + 1];

    float adl = (lane < HEADS) ? g_ad[gw * HEADS + lane] : 0.f;
    float ssum = 0.f;
    if (lane < HEADS)
        for (int i = beg; i < end; i++) {
            int src = g_csr_src[i];
            ssum += expf(leaky(g_as[src * HEADS + lane] + adl, 0.2f));
        }
    float inv = (lane < HEADS) ? 1.f / fmaxf(ssum, 1e-16f) : 0.f;

    int h0[3], pos[3], valid[3];
    #pragma unroll
    for (int j = 0; j < 3; j++) {
        int f4 = lane + 32 * j;
        valid[j] = (f4 < XTS / 8);
        int f0 = f4 * 8;
        int hh = f0 / FHEAD; if (hh > 9) hh = 9;
        h0[j] = hh;
        pos[j] = (hh + 1) * FHEAD - f0;
    }

    float acc[3][8] = {};

    for (int i = beg; i < end; i++) {
        int src = g_csr_src[i];
        if (lane < 12)
            sal[wl][lane] = (lane < HEADS)
                ? expf(leaky(g_as[src * HEADS + lane] + adl, 0.2f)) * inv : 0.f;
        __syncwarp();
        const float4* xs = (const float4*)(g_xth + (long)src * XTS);
        #pragma unroll
        for (int j = 0; j < 3; j++) {
            if (!valid[j]) continue;
            float4 raw = xs[lane + 32 * j];
            const __half2* hp = (const __half2*)&raw;
            float s0 = sal[wl][h0[j]], s1 = sal[wl][h0[j] + 1];
            #pragma unroll
            for (int k = 0; k < 4; k++) {
                float2 v = __half22float2(hp[k]);
                acc[j][2 * k + 0] += v.x * (2 * k     < pos[j] ? s0 : s1);
                acc[j][2 * k + 1] += v.y * (2 * k + 1 < pos[j] ? s0 : s1);
            }
        }
        __syncwarp();
    }

    __half* hd = g_h1h + (long)gw * XTS;
    #pragma unroll
    for (int j = 0; j < 3; j++) {
        if (!valid[j]) continue;
        int f0 = (lane + 32 * j) * 8;
        __half2 o[4];
        #pragma unroll
        for (int k = 0; k < 8; k++) {
            int f = f0 + k;
            float v = (f < D1) ? leaky(acc[j][k] + b_gat[f], 0.01f) : 0.f;
            ((__half*)o)[k] = __float2half_rn(v);
        }
        *(float4*)(hd + f0) = *(float4*)o;
    }
}

// ---------------- GCN gather (fp16, warp per node) -> fp16 agg -------------------
__global__ void gcn_gather_kernel() {
    int gw = (blockIdx.x * blockDim.x + threadIdx.x) >> 5;
    int lane = threadIdx.x & 31;
    if (gw >= N_NODES) return;
    int beg = g_rowptr[gw], end = g_rowptr[gw + 1];
    float dd = g_dinv[gw];

    float acc[3][8] = {};
    int valid[3];
    #pragma unroll
    for (int j = 0; j < 3; j++) valid[j] = (lane + 32 * j) < XTS / 8;

    for (int i = beg; i < end; i++) {
        int src = g_csr_src[i];
        float nm = dd * g_dinv[src];
        const float4* hs = (const float4*)(g_h1h + (long)src * XTS);
        #pragma unroll
        for (int j = 0; j < 3; j++) {
            if (!valid[j]) continue;
            float4 raw = hs[lane + 32 * j];
            const __half2* hp = (const __half2*)&raw;
            #pragma unroll
            for (int k = 0; k < 4; k++) {
                float2 v = __half22float2(hp[k]);
                acc[j][2 * k + 0] += v.x * nm;
                acc[j][2 * k + 1] += v.y * nm;
            }
        }
    }

    __half* hr = g_aah + (long)gw * KP_AGG;
    #pragma unroll
    for (int j = 0; j < 3; j++) {
        if (!valid[j]) continue;
        int f0 = (lane + 32 * j) * 8;
        __half2 o[4];
        #pragma unroll
        for (int k = 0; k < 8; k++)
            ((__half*)o)[k] = __float2half_rn(acc[j][k]);
        *(float4*)(hr + f0) = *(float4*)o;
    }
    for (int c = XTS + lane; c < KP_AGG; c += 32)
        hr[c] = __float2half_rn(0.f);
}

// ---------------- tail: sums split-K halves, applies g2 bias + leaky --------------
__global__ void tail_kernel(const float* __restrict__ W1, const float* __restrict__ b1,
                            const float* __restrict__ W2, const float* __restrict__ b2,
                            const float* __restrict__ W3, const float* __restrict__ b3,
                            const float* __restrict__ bg2,
                            float* __restrict__ out) {
    int gw = (blockIdx.x * blockDim.x + threadIdx.x) >> 5;
    int lane = threadIdx.x & 31;
    if (gw >= N_NODES) return;
    float v0 = leaky(g_h4a[gw * 64 + lane] + g_h4b[gw * 64 + lane] + bg2[lane], 0.01f);
    float v1 = leaky(g_h4a[gw * 64 + 32 + lane] + g_h4b[gw * 64 + 32 + lane] + bg2[32 + lane], 0.01f);
    float s = b1[lane];
    #pragma unroll
    for (int k = 0; k < 32; k++) s += __shfl_sync(0xffffffffu, v0, k) * W1[k * 32 + lane];
    #pragma unroll
    for (int k = 0; k < 32; k++) s += __shfl_sync(0xffffffffu, v1, k) * W1[(k + 32) * 32 + lane];
    float u = leaky(s, 0.01f);
    int j = lane & 15;
    float s2 = b2[j];
    #pragma unroll
    for (int k = 0; k < 32; k++) s2 += __shfl_sync(0xffffffffu, u, k) * W2[k * 16 + j];
    float t = leaky(s2, 0.01f);
    float o = (lane < 16) ? t * W3[lane] : 0.f;
    #pragma unroll
    for (int off = 8; off > 0; off >>= 1) o += __shfl_down_sync(0xffffffffu, o, off);
    if (lane == 0) out[gw] = o + b3[0];
}

// ---------------- launch --------------------------------------------------------------
extern "C" void kernel_launch(void* const* d_in, const int* in_sizes, int n_in,
                              void* d_out, int out_size) {
    const float* x     = (const float*)d_in[0];
    const int*   ei    = (const int*)  d_in[1];
    const float* W_gat = (const float*)d_in[2];
    const float* att_s = (const float*)d_in[3];
    const float* att_d = (const float*)d_in[4];
    const float* b_gat = (const float*)d_in[5];
    const float* W_gcn = (const float*)d_in[6];
    const float* b_gcn = (const float*)d_in[7];
    const float* W_g1  = (const float*)d_in[8];
    const float* b_g1  = (const float*)d_in[9];
    const float* W_g2  = (const float*)d_in[10];
    const float* b_g2  = (const float*)d_in[11];
    const float* W_fc1 = (const float*)d_in[12];
    const float* b_fc1 = (const float*)d_in[13];
    const float* W_fc2 = (const float*)d_in[14];
    const float* b_fc2 = (const float*)d_in[15];
    const float* W_out = (const float*)d_in[16];
    const float* b_out = (const float*)d_in[17];
    float* out = (float*)d_out;
    (void)in_sizes; (void)n_in; (void)out_size;

    cudaFuncSetAttribute(mma_gemm<false, false, true>, cudaFuncAttributeMaxDynamicSharedMemorySize, GEMM_SMEM);
    cudaFuncSetAttribute(mma_gemm<true, true, true>,   cudaFuncAttributeMaxDynamicSharedMemorySize, GEMM_SMEM);
    cudaFuncSetAttribute(mma_gemm<false, false, false>, cudaFuncAttributeMaxDynamicSharedMemorySize, GEMM_SMEM);

    float *p_h4a, *p_h4b;
    cudaGetSymbolAddress((void**)&p_h4a, g_h4a);
    cudaGetSymbolAddress((void**)&p_h4b, g_h4b);
    #define HADDR(p, s) __half* p; cudaGetSymbolAddress((void**)&p, s)
    HADDR(axh, g_axh); HADDR(aah, g_aah);
    HADDR(a2h, g_a2h); HADDR(a3h, g_a3h);
    HADDR(bgat, g_bgat); HADDR(bgcn, g_bgcn);
    HADDR(bg1, g_bg1); HADDR(bg2, g_bg2);
    HADDR(xth, g_xth);

    // CSR build
    zero_small_kernel<<<(N_NODES + 255) / 256, 256>>>();
    deg_kernel<<<(E_TOT + 255) / 256, 256>>>(ei);
    scan_kernel<<<1, 1024>>>();
    fill_kernel<<<(E_TOT + 255) / 256, 256>>>(ei);

    // all converts in one launch
    cvt_all_kernel<<<(CVT_TOTAL + 255) / 256, 256>>>(x, W_gat, W_gcn, W_g1, W_g2);

    // GAT linear -> fp16 xt
    mma_gemm<false, false, true><<<dim3(NP_GAT / 128, M_PAD / 128), 256, GEMM_SMEM>>>(
        axh, bgat, nullptr, nullptr, nullptr, xth, KP_X, KP_X / 32, D1, XTS);

    attn_kernel<<<(N_NODES * HEADS + 255) / 256, 256>>>(att_s, att_d);
    gat_gather_kernel<<<(N_NODES * 32 + 255) / 256, 256>>>(b_gat);
    gcn_gather_kernel<<<(N_NODES * 32 + 255) / 256, 256>>>();

    // GCN linear -> fp16
    mma_gemm<true, true, true><<<dim3(NP_GCN / 128, M_PAD / 128), 256, GEMM_SMEM>>>(
        aah, bgcn, b_gcn, nullptr, nullptr, a2h, KP_AGG, KP_AGG / 32, D2, KP_H2);
    // g1 -> fp16
    mma_gemm<true, true, true><<<dim3(NP_G1 / 128, M_PAD / 128), 256, GEMM_SMEM>>>(
        a2h, bg1, b_g1, nullptr, nullptr, a3h, KP_H2, KP_H2 / 32, D3, KP_H3);
    // g2 split-K (z=2): raw partial sums; bias+act applied in tail
    mma_gemm<false, false, false><<<dim3(NP_G2 / 128, M_PAD / 128, 2), 256, GEMM_SMEM>>>(
        a3h, bg2, nullptr, p_h4a, p_h4b, nullptr, KP_H3, KP_H3 / 64, D4, D4);

    tail_kernel<<<(N_NODES * 32 + 255) / 256, 256>>>(
        W_fc1, b_fc1, W_fc2, b_fc2, W_out, b_out, b_g2, out);
}

// round 9
// speedup vs baseline: 1.2505x; 1.2505x over previous
#include <cuda_runtime.h>
#include <cuda_fp16.h>
#include <math.h>
#include <stdint.h>

#define N_NODES 10000
#define N_EDGES 120000
#define E_TOT   130000
#define F_IN    66
#define HEADS   10
#define FHEAD   66
#define D1      660
#define D2      1320
#define D3      1000
#define D4      64
#define M_PAD   10112        // 79 * 128

#define KP_X    96
#define KP_AGG  672          // == XTS (was 704); 21 k-chunks
#define KP_H2   1344
#define KP_H3   1024
#define NP_GAT  768
#define NP_GCN  1408
#define NP_G1   1024
#define NP_G2   128
#define XTS     672          // fp16 row stride for xt / h1

// ---------------- scratch ------------------------------------------------------
__device__             float g_as [N_NODES * HEADS];
__device__             float g_ad [N_NODES * HEADS];
__device__             float g_dinv[N_NODES];
__device__ __align__(16) float g_h4a[N_NODES * D4];
__device__ __align__(16) float g_h4b[N_NODES * D4];

__device__ __align__(16) __half g_xth [N_NODES * XTS];
__device__ __align__(16) __half g_h1h [N_NODES * XTS];

// ---------------- CSR over destination ------------------------------------------
__device__ int g_deg_i [N_NODES];
__device__ int g_fill  [N_NODES];
__device__ int g_rowptr[N_NODES + 1];
__device__ int g_csr_src[E_TOT];

// ---------------- fp16 GEMM buffers ----------------------------------------------
__device__ __align__(16) __half g_axh [M_PAD * KP_X];
__device__ __align__(16) __half g_aah [M_PAD * KP_AGG];
__device__ __align__(16) __half g_a2h [M_PAD * KP_H2];
__device__ __align__(16) __half g_a3h [M_PAD * KP_H3];
__device__ __align__(16) __half g_bgat[NP_GAT * KP_X];
__device__ __align__(16) __half g_bgcn[NP_GCN * KP_AGG];
__device__ __align__(16) __half g_bg1 [NP_G1 * KP_H2];
__device__ __align__(16) __half g_bg2 [NP_G2 * KP_H3];

// ---------------- baseline-PTX helpers -------------------------------------------
__device__ __forceinline__ uint32_t smem_u32(const void* p) {
    uint32_t a;
    asm("{ .reg .u64 t; cvta.to.shared.u64 t, %1; cvt.u32.u64 %0, t; }" : "=r"(a) : "l"(p));
    return a;
}
__device__ __forceinline__ void cp16(uint32_t dst, const void* src) {
    asm volatile("cp.async.cg.shared.global [%0], [%1], 16;" :: "r"(dst), "l"(src));
}
__device__ __forceinline__ void cp_commit() { asm volatile("cp.async.commit_group;"); }
template<int N> __device__ __forceinline__ void cp_wait() {
    asm volatile("cp.async.wait_group %0;" :: "n"(N));
}
__device__ __forceinline__ void ldsm4(uint32_t* r, uint32_t addr) {
    asm volatile("ldmatrix.sync.aligned.m8n8.x4.shared.b16 {%0,%1,%2,%3}, [%4];"
        : "=r"(r[0]), "=r"(r[1]), "=r"(r[2]), "=r"(r[3]) : "r"(addr));
}
__device__ __forceinline__ void mma_f16(float* d, const uint32_t* a, const uint32_t* b) {
    asm volatile("mma.sync.aligned.m16n8k16.row.col.f32.f16.f16.f32 "
        "{%0,%1,%2,%3}, {%4,%5,%6,%7}, {%8,%9}, {%0,%1,%2,%3};"
        : "+f"(d[0]), "+f"(d[1]), "+f"(d[2]), "+f"(d[3])
        : "r"(a[0]), "r"(a[1]), "r"(a[2]), "r"(a[3]), "r"(b[0]), "r"(b[1]));
}

// ---------------- misc ------------------------------------------------------------
__device__ __forceinline__ void edge_sd(const int* ei, int e, int& s, int& d) {
    if (e < N_EDGES) { s = ei[e]; d = ei[N_EDGES + e]; }
    else             { s = d = e - N_EDGES; }
}
__device__ __forceinline__ float leaky(float v, float sl) { return v >= 0.f ? v : sl * v; }

// ---------------- CSR build ---------------------------------------------------------
__global__ void zero_small_kernel() {
    int i = blockIdx.x * blockDim.x + threadIdx.x;
    if (i < N_NODES) { g_deg_i[i] = 0; g_fill[i] = 0; }
}
__global__ void deg_kernel(const int* __restrict__ ei) {
    int e = blockIdx.x * blockDim.x + threadIdx.x;
    if (e >= E_TOT) return;
    int s, d; edge_sd(ei, e, s, d);
    atomicAdd(&g_deg_i[d], 1);
}
__global__ void scan_kernel() {   // single block; also computes dinv
    __shared__ int sm[1024];
    int tid = threadIdx.x;
    int base = tid * 10;
    int local[10]; int sum = 0;
    #pragma unroll
    for (int i = 0; i < 10; i++) {
        int v = (base + i < N_NODES) ? g_deg_i[base + i] : 0;
        if (base + i < N_NODES) g_dinv[base + i] = rsqrtf(fmaxf((float)v, 1.f));
        local[i] = sum; sum += v;
    }
    sm[tid] = sum; __syncthreads();
    for (int off = 1; off < 1024; off <<= 1) {
        int v = (tid >= off) ? sm[tid - off] : 0;
        __syncthreads();
        sm[tid] += v;
        __syncthreads();
    }
    int pre = (tid > 0) ? sm[tid - 1] : 0;
    #pragma unroll
    for (int i = 0; i < 10; i++)
        if (base + i < N_NODES) g_rowptr[base + i] = pre + local[i];
    if (tid == 1023) g_rowptr[N_NODES] = sm[1023];
}
__global__ void fill_kernel(const int* __restrict__ ei) {
    int e = blockIdx.x * blockDim.x + threadIdx.x;
    if (e >= E_TOT) return;
    int s, d; edge_sd(ei, e, s, d);
    int pos = atomicAdd(&g_fill[d], 1);
    g_csr_src[g_rowptr[d] + pos] = s;
}

// ---------------- fused converts (one launch for all 5 regions) -----------------------
#define R0 (NP_GAT * KP_X)
#define R1 (NP_GCN * KP_AGG)
#define R2 (NP_G1 * KP_H2)
#define R3 (NP_G2 * KP_H3)
#define R4 (M_PAD * KP_X)
#define CVT_TOTAL (R0 + R1 + R2 + R3 + R4)

__device__ __forceinline__ void cvtB_one(const float* W, __half* dst, int idx,
                                         int K, int Nn, int Kp) {
    int n = idx / Kp, k = idx - n * Kp;
    float v = (k < K && n < Nn) ? W[(long)k * Nn + n] : 0.f;
    dst[idx] = __float2half_rn(v);
}
__global__ void cvt_all_kernel(const float* __restrict__ x,
                               const float* __restrict__ Wgat, const float* __restrict__ Wgcn,
                               const float* __restrict__ Wg1,  const float* __restrict__ Wg2) {
    int idx = blockIdx.x * blockDim.x + threadIdx.x;
    if (idx >= CVT_TOTAL) return;
    if (idx < R0) { cvtB_one(Wgat, g_bgat, idx, F_IN, D1, KP_X); return; }
    idx -= R0;
    if (idx < R1) { cvtB_one(Wgcn, g_bgcn, idx, D1, D2, KP_AGG); return; }
    idx -= R1;
    if (idx < R2) { cvtB_one(Wg1, g_bg1, idx, D2, D3, KP_H2); return; }
    idx -= R2;
    if (idx < R3) { cvtB_one(Wg2, g_bg2, idx, D3, D4, KP_H3); return; }
    idx -= R3;
    {   // cvtA: x -> g_axh
        int r = idx / KP_X, c = idx - r * KP_X;
        float v = (r < N_NODES && c < F_IN) ? x[(long)r * F_IN + c] : 0.f;
        g_axh[idx] = __float2half_rn(v);
    }
}

// ---------------- HMMA GEMM (single fp16, 4-stage cp.async, 2 CTAs/SM) ----------------
#define TSTRIDE  80
#define B_HI_OFF 10240
#define STAGE_SZ 20480
#define GEMM_SMEM (4 * STAGE_SZ)

__device__ __forceinline__ void fill_stage(uint32_t st,
        const __half* __restrict__ A, const __half* __restrict__ B,
        int m0, int n0, int Kp, int k0, int tid) {
    #pragma unroll
    for (int i = 0; i < 2; i++) {
        int lin = tid + i * 256;
        int r = lin >> 2, cc = lin & 3;
        uint32_t d = st + r * TSTRIDE + cc * 16;
        cp16(d,            (const char*)(A + (long)(m0 + r) * Kp + k0) + cc * 16);
        cp16(d + B_HI_OFF, (const char*)(B + (long)(n0 + r) * Kp + k0) + cc * 16);
    }
    cp_commit();
}

template<bool BIAS, bool ACT, bool SPLIT>
__global__ __launch_bounds__(256, 2)
void mma_gemm(const __half* __restrict__ Ah, const __half* __restrict__ Bh,
              const float* __restrict__ bias, float* __restrict__ C,
              float* __restrict__ C2, __half* __restrict__ Sh,
              int Kp, int chunks, int Nreal, int ldC) {
    extern __shared__ char smem[];
    const uint32_t tile0 = smem_u32(smem);
    const int tid = threadIdx.x, wid = tid >> 5, lane = tid & 31;
    const int m0 = blockIdx.y * 128, n0 = blockIdx.x * 128;
    const int kbase = blockIdx.z * chunks * 32;   // split-K offset
    const int mwoff = (wid >> 1) * 32, nwoff = (wid & 1) * 64;

    const int mat = lane >> 3, mrow = lane & 7;
    uint32_t a_off[2], b_off[4];
    #pragma unroll
    for (int ti = 0; ti < 2; ti++)
        a_off[ti] = (uint32_t)((mwoff + ti * 16 + ((mat & 1) << 3) + mrow) * TSTRIDE
                               + (mat >> 1) * 16);
    #pragma unroll
    for (int nt = 0; nt < 4; nt++)
        b_off[nt] = (uint32_t)((nwoff + nt * 16 + ((mat >> 1) << 3) + mrow) * TSTRIDE
                               + (mat & 1) * 16);

    float acc[2][8][4] = {};

    fill_stage(tile0, Ah, Bh, m0, n0, Kp, kbase, tid);
    if (chunks > 1) fill_stage(tile0 + STAGE_SZ, Ah, Bh, m0, n0, Kp, kbase + 32, tid);
    if (chunks > 2) fill_stage(tile0 + 2 * STAGE_SZ, Ah, Bh, m0, n0, Kp, kbase + 64, tid);

    for (int c = 0; c < chunks; c++) {
        if (c + 2 < chunks)      cp_wait<2>();
        else if (c + 1 < chunks) cp_wait<1>();
        else                     cp_wait<0>();
        __syncthreads();
        if (c + 3 < chunks)
            fill_stage(tile0 + ((c + 3) & 3) * STAGE_SZ, Ah, Bh,
                       m0, n0, Kp, kbase + (c + 3) * 32, tid);
        uint32_t sb = tile0 + (c & 3) * STAGE_SZ;
        #pragma unroll
        for (int kh = 0; kh < 2; kh++) {
            uint32_t ah[2][4], bh[4][4];
            #pragma unroll
            for (int ti = 0; ti < 2; ti++)
                ldsm4(ah[ti], sb + a_off[ti] + kh * 32);
            #pragma unroll
            for (int nt = 0; nt < 4; nt++)
                ldsm4(bh[nt], sb + B_HI_OFF + b_off[nt] + kh * 32);
            #pragma unroll
            for (int ti = 0; ti < 2; ti++)
                #pragma unroll
                for (int nt = 0; nt < 8; nt++)
                    mma_f16(acc[ti][nt], ah[ti], &bh[nt >> 1][(nt & 1) * 2]);
        }
    }

    float* Cout = (blockIdx.z == 0) ? C : C2;
    const int lr = lane >> 2, lc = (lane & 3) * 2;
    #pragma unroll
    for (int ti = 0; ti < 2; ti++)
        #pragma unroll
        for (int rp = 0; rp < 2; rp++) {
            int gr = m0 + mwoff + ti * 16 + rp * 8 + lr;
            if (gr >= N_NODES) continue;
            if (!SPLIT) {
                float* crow = Cout + (long)gr * ldC;
                #pragma unroll
                for (int nt = 0; nt < 8; nt++) {
                    int gc = n0 + nwoff + nt * 8 + lc;
                    float v0 = acc[ti][nt][rp * 2 + 0];
                    float v1 = acc[ti][nt][rp * 2 + 1];
                    if (gc < Nreal) {
                        if (BIAS) v0 += bias[gc];
                        if (ACT)  v0 = leaky(v0, 0.01f);
                        crow[gc] = v0;
                    }
                    if (gc + 1 < Nreal) {
                        if (BIAS) v1 += bias[gc + 1];
                        if (ACT)  v1 = leaky(v1, 0.01f);
                        crow[gc + 1] = v1;
                    }
                }
            } else {
                __half* hr = Sh + (long)gr * ldC;
                #pragma unroll
                for (int nt = 0; nt < 8; nt++) {
                    int gc = n0 + nwoff + nt * 8 + lc;
                    if (gc >= ldC) continue;
                    float v0 = 0.f, v1 = 0.f;
                    if (gc < Nreal) {
                        v0 = acc[ti][nt][rp * 2 + 0];
                        if (BIAS) v0 += bias[gc];
                        if (ACT)  v0 = leaky(v0, 0.01f);
                    }
                    if (gc + 1 < Nreal) {
                        v1 = acc[ti][nt][rp * 2 + 1];
                        if (BIAS) v1 += bias[gc + 1];
                        if (ACT)  v1 = leaky(v1, 0.01f);
                    }
                    __half2 hp;
                    hp.x = __float2half_rn(v0);
                    hp.y = __float2half_rn(v1);
                    *(__half2*)(hr + gc) = hp;
                }
            }
        }
}

// ---------------- attention coefficients (fp16 xt) -----------------------------
__global__ void attn_kernel(const float* __restrict__ att_src,
                            const float* __restrict__ att_dst) {
    int idx = blockIdx.x * blockDim.x + threadIdx.x;
    if (idx >= N_NODES * HEADS) return;
    int n = idx / HEADS, h = idx % HEADS;
    const __half* xr = g_xth + (long)n * XTS + h * FHEAD;
    const float* as = att_src + h * FHEAD;
    const float* ad = att_dst + h * FHEAD;
    float s = 0.f, d = 0.f;
    #pragma unroll
    for (int f = 0; f < FHEAD; f++) {
        float v = __half2float(xr[f]);
        s += v * as[f]; d += v * ad[f];
    }
    g_as[idx] = s; g_ad[idx] = d;
}

// ---------------- GAT gather (fp16 features, warp per dst node) -----------------
__global__ void gat_gather_kernel(const float* __restrict__ b_gat) {
    int gw = (blockIdx.x * blockDim.x + threadIdx.x) >> 5;
    int lane = threadIdx.x & 31;
    int wl = threadIdx.x >> 5;
    __shared__ float sal[8][12];
    if (gw >= N_NODES) return;
    int beg = g_rowptr[gw], end = g_rowptr[gw + 1];

    float adl = (lane < HEADS) ? g_ad[gw * HEADS + lane] : 0.f;
    float ssum = 0.f;
    if (lane < HEADS)
        for (int i = beg; i < end; i++) {
            int src = g_csr_src[i];
            ssum += expf(leaky(g_as[src * HEADS + lane] + adl, 0.2f));
        }
    float inv = (lane < HEADS) ? 1.f / fmaxf(ssum, 1e-16f) : 0.f;

    int h0[3], pos[3], valid[3];
    #pragma unroll
    for (int j = 0; j < 3; j++) {
        int f4 = lane + 32 * j;
        valid[j] = (f4 < XTS / 8);
        int f0 = f4 * 8;
        int hh = f0 / FHEAD; if (hh > 9) hh = 9;
        h0[j] = hh;
        pos[j] = (hh + 1) * FHEAD - f0;
    }

    float acc[3][8] = {};

    for (int i = beg; i < end; i++) {
        int src = g_csr_src[i];
        if (lane < 12)
            sal[wl][lane] = (lane < HEADS)
                ? expf(leaky(g_as[src * HEADS + lane] + adl, 0.2f)) * inv : 0.f;
        __syncwarp();
        const float4* xs = (const float4*)(g_xth + (long)src * XTS);
        #pragma unroll
        for (int j = 0; j < 3; j++) {
            if (!valid[j]) continue;
            float4 raw = xs[lane + 32 * j];
            const __half2* hp = (const __half2*)&raw;
            float s0 = sal[wl][h0[j]], s1 = sal[wl][h0[j] + 1];
            #pragma unroll
            for (int k = 0; k < 4; k++) {
                float2 v = __half22float2(hp[k]);
                acc[j][2 * k + 0] += v.x * (2 * k     < pos[j] ? s0 : s1);
                acc[j][2 * k + 1] += v.y * (2 * k + 1 < pos[j] ? s0 : s1);
            }
        }
        __syncwarp();
    }

    __half* hd = g_h1h + (long)gw * XTS;
    #pragma unroll
    for (int j = 0; j < 3; j++) {
        if (!valid[j]) continue;
        int f0 = (lane + 32 * j) * 8;
        __half2 o[4];
        #pragma unroll
        for (int k = 0; k < 8; k++) {
            int f = f0 + k;
            float v = (f < D1) ? leaky(acc[j][k] + b_gat[f], 0.01f) : 0.f;
            ((__half*)o)[k] = __float2half_rn(v);
        }
        *(float4*)(hd + f0) = *(float4*)o;
    }
}

// ---------------- GCN gather (fp16, warp per node) -> fp16 agg -------------------
__global__ void gcn_gather_kernel() {
    int gw = (blockIdx.x * blockDim.x + threadIdx.x) >> 5;
    int lane = threadIdx.x & 31;
    if (gw >= N_NODES) return;
    int beg = g_rowptr[gw], end = g_rowptr[gw + 1];
    float dd = g_dinv[gw];

    float acc[3][8] = {};
    int valid[3];
    #pragma unroll
    for (int j = 0; j < 3; j++) valid[j] = (lane + 32 * j) < XTS / 8;

    for (int i = beg; i < end; i++) {
        int src = g_csr_src[i];
        float nm = dd * g_dinv[src];
        const float4* hs = (const float4*)(g_h1h + (long)src * XTS);
        #pragma unroll
        for (int j = 0; j < 3; j++) {
            if (!valid[j]) continue;
            float4 raw = hs[lane + 32 * j];
            const __half2* hp = (const __half2*)&raw;
            #pragma unroll
            for (int k = 0; k < 4; k++) {
                float2 v = __half22float2(hp[k]);
                acc[j][2 * k + 0] += v.x * nm;
                acc[j][2 * k + 1] += v.y * nm;
            }
        }
    }

    // KP_AGG == XTS: rows are written wall-to-wall, no pad loop needed
    __half* hr = g_aah + (long)gw * KP_AGG;
    #pragma unroll
    for (int j = 0; j < 3; j++) {
        if (!valid[j]) continue;
        int f0 = (lane + 32 * j) * 8;
        __half2 o[4];
        #pragma unroll
        for (int k = 0; k < 8; k++)
            ((__half*)o)[k] = __float2half_rn(acc[j][k]);
        *(float4*)(hr + f0) = *(float4*)o;
    }
}

// ---------------- tail: sums split-K halves, applies g2 bias + leaky --------------
__global__ void tail_kernel(const float* __restrict__ W1, const float* __restrict__ b1,
                            const float* __restrict__ W2, const float* __restrict__ b2,
                            const float* __restrict__ W3, const float* __restrict__ b3,
                            const float* __restrict__ bg2,
                            float* __restrict__ out) {
    int gw = (blockIdx.x * blockDim.x + threadIdx.x) >> 5;
    int lane = threadIdx.x & 31;
    if (gw >= N_NODES) return;
    float v0 = leaky(g_h4a[gw * 64 + lane] + g_h4b[gw * 64 + lane] + bg2[lane], 0.01f);
    float v1 = leaky(g_h4a[gw * 64 + 32 + lane] + g_h4b[gw * 64 + 32 + lane] + bg2[32 + lane], 0.01f);
    float s = b1[lane];
    #pragma unroll
    for (int k = 0; k < 32; k++) s += __shfl_sync(0xffffffffu, v0, k) * W1[k * 32 + lane];
    #pragma unroll
    for (int k = 0; k < 32; k++) s += __shfl_sync(0xffffffffu, v1, k) * W1[(k + 32) * 32 + lane];
    float u = leaky(s, 0.01f);
    int j = lane & 15;
    float s2 = b2[j];
    #pragma unroll
    for (int k = 0; k < 32; k++) s2 += __shfl_sync(0xffffffffu, u, k) * W2[k * 16 + j];
    float t = leaky(s2, 0.01f);
    float o = (lane < 16) ? t * W3[lane] : 0.f;
    #pragma unroll
    for (int off = 8; off > 0; off >>= 1) o += __shfl_down_sync(0xffffffffu, o, off);
    if (lane == 0) out[gw] = o + b3[0];
}

// ---------------- launch --------------------------------------------------------------
extern "C" void kernel_launch(void* const* d_in, const int* in_sizes, int n_in,
                              void* d_out, int out_size) {
    const float* x     = (const float*)d_in[0];
    const int*   ei    = (const int*)  d_in[1];
    const float* W_gat = (const float*)d_in[2];
    const float* att_s = (const float*)d_in[3];
    const float* att_d = (const float*)d_in[4];
    const float* b_gat = (const float*)d_in[5];
    const float* W_gcn = (const float*)d_in[6];
    const float* b_gcn = (const float*)d_in[7];
    const float* W_g1  = (const float*)d_in[8];
    const float* b_g1  = (const float*)d_in[9];
    const float* W_g2  = (const float*)d_in[10];
    const float* b_g2  = (const float*)d_in[11];
    const float* W_fc1 = (const float*)d_in[12];
    const float* b_fc1 = (const float*)d_in[13];
    const float* W_fc2 = (const float*)d_in[14];
    const float* b_fc2 = (const float*)d_in[15];
    const float* W_out = (const float*)d_in[16];
    const float* b_out = (const float*)d_in[17];
    float* out = (float*)d_out;
    (void)in_sizes; (void)n_in; (void)out_size;

    cudaFuncSetAttribute(mma_gemm<false, false, true>, cudaFuncAttributeMaxDynamicSharedMemorySize, GEMM_SMEM);
    cudaFuncSetAttribute(mma_gemm<true, true, true>,   cudaFuncAttributeMaxDynamicSharedMemorySize, GEMM_SMEM);
    cudaFuncSetAttribute(mma_gemm<false, false, false>, cudaFuncAttributeMaxDynamicSharedMemorySize, GEMM_SMEM);

    float *p_h4a, *p_h4b;
    cudaGetSymbolAddress((void**)&p_h4a, g_h4a);
    cudaGetSymbolAddress((void**)&p_h4b, g_h4b);
    #define HADDR(p, s) __half* p; cudaGetSymbolAddress((void**)&p, s)
    HADDR(axh, g_axh); HADDR(aah, g_aah);
    HADDR(a2h, g_a2h); HADDR(a3h, g_a3h);
    HADDR(bgat, g_bgat); HADDR(bgcn, g_bgcn);
    HADDR(bg1, g_bg1); HADDR(bg2, g_bg2);
    HADDR(xth, g_xth);

    // CSR build
    zero_small_kernel<<<(N_NODES + 255) / 256, 256>>>();
    deg_kernel<<<(E_TOT + 255) / 256, 256>>>(ei);
    scan_kernel<<<1, 1024>>>();
    fill_kernel<<<(E_TOT + 255) / 256, 256>>>(ei);

    // all converts in one launch
    cvt_all_kernel<<<(CVT_TOTAL + 255) / 256, 256>>>(x, W_gat, W_gcn, W_g1, W_g2);

    // GAT linear -> fp16 xt
    mma_gemm<false, false, true><<<dim3(NP_GAT / 128, M_PAD / 128), 256, GEMM_SMEM>>>(
        axh, bgat, nullptr, nullptr, nullptr, xth, KP_X, KP_X / 32, D1, XTS);

    attn_kernel<<<(N_NODES * HEADS + 255) / 256, 256>>>(att_s, att_d);
    gat_gather_kernel<<<(N_NODES * 32 + 255) / 256, 256>>>(b_gat);
    gcn_gather_kernel<<<(N_NODES * 32 + 255) / 256, 256>>>();

    // GCN linear -> fp16
    mma_gemm<true, true, true><<<dim3(NP_GCN / 128, M_PAD / 128), 256, GEMM_SMEM>>>(
        aah, bgcn, b_gcn, nullptr, nullptr, a2h, KP_AGG, KP_AGG / 32, D2, KP_H2);
    // g1 -> fp16
    mma_gemm<true, true, true><<<dim3(NP_G1 / 128, M_PAD / 128), 256, GEMM_SMEM>>>(
        a2h, bg1, b_g1, nullptr, nullptr, a3h, KP_H2, KP_H2 / 32, D3, KP_H3);
    // g2 split-K (z=2): raw partial sums; bias+act applied in tail
    mma_gemm<false, false, false><<<dim3(NP_G2 / 128, M_PAD / 128, 2), 256, GEMM_SMEM>>>(
        a3h, bg2, nullptr, p_h4a, p_h4b, nullptr, KP_H3, KP_H3 / 64, D4, D4);

    tail_kernel<<<(N_NODES * 32 + 255) / 256, 256>>>(
        W_fc1, b_fc1, W_fc2, b_fc2, W_out, b_out, b_g2, out);
}

// round 10
// speedup vs baseline: 1.2627x; 1.0098x over previous
#include <cuda_runtime.h>
#include <cuda_fp16.h>
#include <math.h>
#include <stdint.h>

#define N_NODES 10000
#define N_EDGES 120000
#define E_TOT   130000
#define F_IN    66
#define HEADS   10
#define FHEAD   66
#define D1      660
#define D2      1320
#define D3      1000
#define D4      64
#define M_PAD   10112        // 79 * 128

#define KP_X    96
#define KP_AGG  672
#define KP_H2   1344
#define KP_H3   1024
#define NP_GAT  768
#define NP_GCN  1408
#define NP_G1   1024
#define NP_G2   128
#define XTS     672          // fp16 row stride for xt / h1

// ---------------- scratch ------------------------------------------------------
__device__             float g_as [N_NODES * HEADS];
__device__             float g_ad [N_NODES * HEADS];
__device__             float g_ws [HEADS * F_IN];
__device__             float g_wd [HEADS * F_IN];
__device__             float g_dinv[N_NODES];
__device__ __align__(16) float g_h4a[N_NODES * D4];
__device__ __align__(16) float g_h4b[N_NODES * D4];

__device__ __align__(16) __half g_xth [N_NODES * XTS];
__device__ __align__(16) __half g_h1h [N_NODES * XTS];

// ---------------- CSR over destination ------------------------------------------
__device__ int g_deg_i [N_NODES];
__device__ int g_fill  [N_NODES];
__device__ int g_rowptr[N_NODES + 1];
__device__ int g_csr_src[E_TOT];

// ---------------- fp16 GEMM buffers ----------------------------------------------
__device__ __align__(16) __half g_axh [M_PAD * KP_X];
__device__ __align__(16) __half g_aah [M_PAD * KP_AGG];
__device__ __align__(16) __half g_a2h [M_PAD * KP_H2];
__device__ __align__(16) __half g_a3h [M_PAD * KP_H3];
__device__ __align__(16) __half g_bgat[NP_GAT * KP_X];
__device__ __align__(16) __half g_bgcn[NP_GCN * KP_AGG];
__device__ __align__(16) __half g_bg1 [NP_G1 * KP_H2];
__device__ __align__(16) __half g_bg2 [NP_G2 * KP_H3];

// ---------------- baseline-PTX helpers -------------------------------------------
__device__ __forceinline__ uint32_t smem_u32(const void* p) {
    uint32_t a;
    asm("{ .reg .u64 t; cvta.to.shared.u64 t, %1; cvt.u32.u64 %0, t; }" : "=r"(a) : "l"(p));
    return a;
}
__device__ __forceinline__ void cp16(uint32_t dst, const void* src) {
    asm volatile("cp.async.cg.shared.global [%0], [%1], 16;" :: "r"(dst), "l"(src));
}
__device__ __forceinline__ void cp_commit() { asm volatile("cp.async.commit_group;"); }
template<int N> __device__ __forceinline__ void cp_wait() {
    asm volatile("cp.async.wait_group %0;" :: "n"(N));
}
__device__ __forceinline__ void ldsm4(uint32_t* r, uint32_t addr) {
    asm volatile("ldmatrix.sync.aligned.m8n8.x4.shared.b16 {%0,%1,%2,%3}, [%4];"
        : "=r"(r[0]), "=r"(r[1]), "=r"(r[2]), "=r"(r[3]) : "r"(addr));
}
__device__ __forceinline__ void mma_f16(float* d, const uint32_t* a, const uint32_t* b) {
    asm volatile("mma.sync.aligned.m16n8k16.row.col.f32.f16.f16.f32 "
        "{%0,%1,%2,%3}, {%4,%5,%6,%7}, {%8,%9}, {%0,%1,%2,%3};"
        : "+f"(d[0]), "+f"(d[1]), "+f"(d[2]), "+f"(d[3])
        : "r"(a[0]), "r"(a[1]), "r"(a[2]), "r"(a[3]), "r"(b[0]), "r"(b[1]));
}

// ---------------- misc ------------------------------------------------------------
__device__ __forceinline__ void edge_sd(const int* ei, int e, int& s, int& d) {
    if (e < N_EDGES) { s = ei[e]; d = ei[N_EDGES + e]; }
    else             { s = d = e - N_EDGES; }
}
__device__ __forceinline__ float leaky(float v, float sl) { return v >= 0.f ? v : sl * v; }

// ---------------- CSR build ---------------------------------------------------------
__global__ void zero_small_kernel() {
    int i = blockIdx.x * blockDim.x + threadIdx.x;
    if (i < N_NODES) { g_deg_i[i] = 0; g_fill[i] = 0; }
}
__global__ void deg_kernel(const int* __restrict__ ei) {
    int e = blockIdx.x * blockDim.x + threadIdx.x;
    if (e >= E_TOT) return;
    int s, d; edge_sd(ei, e, s, d);
    atomicAdd(&g_deg_i[d], 1);
}
__global__ void scan_kernel() {   // single block; also computes dinv
    __shared__ int sm[1024];
    int tid = threadIdx.x;
    int base = tid * 10;
    int local[10]; int sum = 0;
    #pragma unroll
    for (int i = 0; i < 10; i++) {
        int v = (base + i < N_NODES) ? g_deg_i[base + i] : 0;
        if (base + i < N_NODES) g_dinv[base + i] = rsqrtf(fmaxf((float)v, 1.f));
        local[i] = sum; sum += v;
    }
    sm[tid] = sum; __syncthreads();
    for (int off = 1; off < 1024; off <<= 1) {
        int v = (tid >= off) ? sm[tid - off] : 0;
        __syncthreads();
        sm[tid] += v;
        __syncthreads();
    }
    int pre = (tid > 0) ? sm[tid - 1] : 0;
    #pragma unroll
    for (int i = 0; i < 10; i++)
        if (base + i < N_NODES) g_rowptr[base + i] = pre + local[i];
    if (tid == 1023) g_rowptr[N_NODES] = sm[1023];
}
__global__ void fill_kernel(const int* __restrict__ ei) {
    int e = blockIdx.x * blockDim.x + threadIdx.x;
    if (e >= E_TOT) return;
    int s, d; edge_sd(ei, e, s, d);
    int pos = atomicAdd(&g_fill[d], 1);
    g_csr_src[g_rowptr[d] + pos] = s;
}

// ---------------- attn hoist: w = W_gat @ att (per head), then a = x @ w ------------
__global__ void ws_kernel(const float* __restrict__ Wgat,
                          const float* __restrict__ att_s, const float* __restrict__ att_d) {
    int idx = blockIdx.x * blockDim.x + threadIdx.x;
    if (idx >= HEADS * F_IN) return;
    int h = idx / F_IN, i = idx - h * F_IN;
    const float* wrow = Wgat + (long)i * D1 + h * FHEAD;
    const float* as = att_s + h * FHEAD;
    const float* ad = att_d + h * FHEAD;
    float s = 0.f, d = 0.f;
    #pragma unroll
    for (int f = 0; f < FHEAD; f++) { float w = wrow[f]; s += w * as[f]; d += w * ad[f]; }
    g_ws[idx] = s; g_wd[idx] = d;
}
__global__ void asd_kernel(const float* __restrict__ x) {
    int idx = blockIdx.x * blockDim.x + threadIdx.x;
    if (idx >= N_NODES * HEADS) return;
    int n = idx / HEADS, h = idx - n * HEADS;
    const float* xr = x + (long)n * F_IN;
    const float* ws = g_ws + h * F_IN;
    const float* wd = g_wd + h * F_IN;
    float s = 0.f, d = 0.f;
    #pragma unroll
    for (int i = 0; i < F_IN; i++) { float v = xr[i]; s += v * ws[i]; d += v * wd[i]; }
    g_as[idx] = s; g_ad[idx] = d;
}

// ---------------- converts: critical (axh,bgat) and rest (bgcn,bg1,bg2) --------------
#define R0 (NP_GAT * KP_X)
#define R4 (M_PAD * KP_X)
#define CVT_CRIT (R0 + R4)
#define R1 (NP_GCN * KP_AGG)
#define R2 (NP_G1 * KP_H2)
#define R3 (NP_G2 * KP_H3)
#define CVT_REST (R1 + R2 + R3)

__device__ __forceinline__ void cvtB_one(const float* W, __half* dst, int idx,
                                         int K, int Nn, int Kp) {
    int n = idx / Kp, k = idx - n * Kp;
    float v = (k < K && n < Nn) ? W[(long)k * Nn + n] : 0.f;
    dst[idx] = __float2half_rn(v);
}
__global__ void cvt_crit_kernel(const float* __restrict__ x, const float* __restrict__ Wgat) {
    int idx = blockIdx.x * blockDim.x + threadIdx.x;
    if (idx >= CVT_CRIT) return;
    if (idx < R0) { cvtB_one(Wgat, g_bgat, idx, F_IN, D1, KP_X); return; }
    idx -= R0;
    int r = idx / KP_X, c = idx - r * KP_X;
    float v = (r < N_NODES && c < F_IN) ? x[(long)r * F_IN + c] : 0.f;
    g_axh[idx] = __float2half_rn(v);
}
__global__ void cvt_rest_kernel(const float* __restrict__ Wgcn,
                                const float* __restrict__ Wg1, const float* __restrict__ Wg2) {
    int idx = blockIdx.x * blockDim.x + threadIdx.x;
    if (idx >= CVT_REST) return;
    if (idx < R1) { cvtB_one(Wgcn, g_bgcn, idx, D1, D2, KP_AGG); return; }
    idx -= R1;
    if (idx < R2) { cvtB_one(Wg1, g_bg1, idx, D2, D3, KP_H2); return; }
    idx -= R2;
    cvtB_one(Wg2, g_bg2, idx, D3, D4, KP_H3);
}

// ---------------- HMMA GEMM (single fp16, 4-stage cp.async, 2 CTAs/SM) ----------------
#define TSTRIDE  80
#define B_HI_OFF 10240
#define STAGE_SZ 20480
#define GEMM_SMEM (4 * STAGE_SZ)

__device__ __forceinline__ void fill_stage(uint32_t st,
        const __half* __restrict__ A, const __half* __restrict__ B,
        int m0, int n0, int Kp, int k0, int tid) {
    #pragma unroll
    for (int i = 0; i < 2; i++) {
        int lin = tid + i * 256;
        int r = lin >> 2, cc = lin & 3;
        uint32_t d = st + r * TSTRIDE + cc * 16;
        cp16(d,            (const char*)(A + (long)(m0 + r) * Kp + k0) + cc * 16);
        cp16(d + B_HI_OFF, (const char*)(B + (long)(n0 + r) * Kp + k0) + cc * 16);
    }
    cp_commit();
}

template<bool BIAS, bool ACT, bool SPLIT>
__global__ __launch_bounds__(256, 2)
void mma_gemm(const __half* __restrict__ Ah, const __half* __restrict__ Bh,
              const float* __restrict__ bias, float* __restrict__ C,
              float* __restrict__ C2, __half* __restrict__ Sh,
              int Kp, int chunks, int Nreal, int ldC) {
    extern __shared__ char smem[];
    const uint32_t tile0 = smem_u32(smem);
    const int tid = threadIdx.x, wid = tid >> 5, lane = tid & 31;
    const int m0 = blockIdx.y * 128, n0 = blockIdx.x * 128;
    const int kbase = blockIdx.z * chunks * 32;
    const int mwoff = (wid >> 1) * 32, nwoff = (wid & 1) * 64;

    const int mat = lane >> 3, mrow = lane & 7;
    uint32_t a_off[2], b_off[4];
    #pragma unroll
    for (int ti = 0; ti < 2; ti++)
        a_off[ti] = (uint32_t)((mwoff + ti * 16 + ((mat & 1) << 3) + mrow) * TSTRIDE
                               + (mat >> 1) * 16);
    #pragma unroll
    for (int nt = 0; nt < 4; nt++)
        b_off[nt] = (uint32_t)((nwoff + nt * 16 + ((mat >> 1) << 3) + mrow) * TSTRIDE
                               + (mat & 1) * 16);

    float acc[2][8][4] = {};

    fill_stage(tile0, Ah, Bh, m0, n0, Kp, kbase, tid);
    if (chunks > 1) fill_stage(tile0 + STAGE_SZ, Ah, Bh, m0, n0, Kp, kbase + 32, tid);
    if (chunks > 2) fill_stage(tile0 + 2 * STAGE_SZ, Ah, Bh, m0, n0, Kp, kbase + 64, tid);

    for (int c = 0; c < chunks; c++) {
        if (c + 2 < chunks)      cp_wait<2>();
        else if (c + 1 < chunks) cp_wait<1>();
        else                     cp_wait<0>();
        __syncthreads();
        if (c + 3 < chunks)
            fill_stage(tile0 + ((c + 3) & 3) * STAGE_SZ, Ah, Bh,
                       m0, n0, Kp, kbase + (c + 3) * 32, tid);
        uint32_t sb = tile0 + (c & 3) * STAGE_SZ;
        #pragma unroll
        for (int kh = 0; kh < 2; kh++) {
            uint32_t ah[2][4], bh[4][4];
            #pragma unroll
            for (int ti = 0; ti < 2; ti++)
                ldsm4(ah[ti], sb + a_off[ti] + kh * 32);
            #pragma unroll
            for (int nt = 0; nt < 4; nt++)
                ldsm4(bh[nt], sb + B_HI_OFF + b_off[nt] + kh * 32);
            #pragma unroll
            for (int ti = 0; ti < 2; ti++)
                #pragma unroll
                for (int nt = 0; nt < 8; nt++)
                    mma_f16(acc[ti][nt], ah[ti], &bh[nt >> 1][(nt & 1) * 2]);
        }
    }

    float* Cout = (blockIdx.z == 0) ? C : C2;
    const int lr = lane >> 2, lc = (lane & 3) * 2;
    #pragma unroll
    for (int ti = 0; ti < 2; ti++)
        #pragma unroll
        for (int rp = 0; rp < 2; rp++) {
            int gr = m0 + mwoff + ti * 16 + rp * 8 + lr;
            if (gr >= N_NODES) continue;
            if (!SPLIT) {
                float* crow = Cout + (long)gr * ldC;
                #pragma unroll
                for (int nt = 0; nt < 8; nt++) {
                    int gc = n0 + nwoff + nt * 8 + lc;
                    float v0 = acc[ti][nt][rp * 2 + 0];
                    float v1 = acc[ti][nt][rp * 2 + 1];
                    if (gc < Nreal) {
                        if (BIAS) v0 += bias[gc];
                        if (ACT)  v0 = leaky(v0, 0.01f);
                        crow[gc] = v0;
                    }
                    if (gc + 1 < Nreal) {
                        if (BIAS) v1 += bias[gc + 1];
                        if (ACT)  v1 = leaky(v1, 0.01f);
                        crow[gc + 1] = v1;
                    }
                }
            } else {
                __half* hr = Sh + (long)gr * ldC;
                #pragma unroll
                for (int nt = 0; nt < 8; nt++) {
                    int gc = n0 + nwoff + nt * 8 + lc;
                    if (gc >= ldC) continue;
                    float v0 = 0.f, v1 = 0.f;
                    if (gc < Nreal) {
                        v0 = acc[ti][nt][rp * 2 + 0];
                        if (BIAS) v0 += bias[gc];
                        if (ACT)  v0 = leaky(v0, 0.01f);
                    }
                    if (gc + 1 < Nreal) {
                        v1 = acc[ti][nt][rp * 2 + 1];
                        if (BIAS) v1 += bias[gc + 1];
                        if (ACT)  v1 = leaky(v1, 0.01f);
                    }
                    __half2 hp;
                    hp.x = __float2half_rn(v0);
                    hp.y = __float2half_rn(v1);
                    *(__half2*)(hr + gc) = hp;
                }
            }
        }
}

// ---------------- GAT gather (fp16 features, warp per dst node) -----------------
__global__ void gat_gather_kernel(const float* __restrict__ b_gat) {
    int gw = (blockIdx.x * blockDim.x + threadIdx.x) >> 5;
    int lane = threadIdx.x & 31;
    int wl = threadIdx.x >> 5;
    __shared__ float sal[8][12];
    if (gw >= N_NODES) return;
    int beg = g_rowptr[gw], end = g_rowptr[gw + 1];

    float adl = (lane < HEADS) ? g_ad[gw * HEADS + lane] : 0.f;
    float ssum = 0.f;
    if (lane < HEADS)
        for (int i = beg; i < end; i++) {
            int src = g_csr_src[i];
            ssum += expf(leaky(g_as[src * HEADS + lane] + adl, 0.2f));
        }
    float inv = (lane < HEADS) ? 1.f / fmaxf(ssum, 1e-16f) : 0.f;

    int h0[3], pos[3], valid[3];
    #pragma unroll
    for (int j = 0; j < 3; j++) {
        int f4 = lane + 32 * j;
        valid[j] = (f4 < XTS / 8);
        int f0 = f4 * 8;
        int hh = f0 / FHEAD; if (hh > 9) hh = 9;
        h0[j] = hh;
        pos[j] = (hh + 1) * FHEAD - f0;
    }

    float acc[3][8] = {};

    for (int i = beg; i < end; i++) {
        int src = g_csr_src[i];
        if (lane < 12)
            sal[wl][lane] = (lane < HEADS)
                ? expf(leaky(g_as[src * HEADS + lane] + adl, 0.2f)) * inv : 0.f;
        __syncwarp();
        const float4* xs = (const float4*)(g_xth + (long)src * XTS);
        #pragma unroll
        for (int j = 0; j < 3; j++) {
            if (!valid[j]) continue;
            float4 raw = xs[lane + 32 * j];
            const __half2* hp = (const __half2*)&raw;
            float s0 = sal[wl][h0[j]], s1 = sal[wl][h0[j] + 1];
            #pragma unroll
            for (int k = 0; k < 4; k++) {
                float2 v = __half22float2(hp[k]);
                acc[j][2 * k + 0] += v.x * (2 * k     < pos[j] ? s0 : s1);
                acc[j][2 * k + 1] += v.y * (2 * k + 1 < pos[j] ? s0 : s1);
            }
        }
        __syncwarp();
    }

    __half* hd = g_h1h + (long)gw * XTS;
    #pragma unroll
    for (int j = 0; j < 3; j++) {
        if (!valid[j]) continue;
        int f0 = (lane + 32 * j) * 8;
        __half2 o[4];
        #pragma unroll
        for (int k = 0; k < 8; k++) {
            int f = f0 + k;
            float v = (f < D1) ? leaky(acc[j][k] + b_gat[f], 0.01f) : 0.f;
            ((__half*)o)[k] = __float2half_rn(v);
        }
        *(float4*)(hd + f0) = *(float4*)o;
    }
}

// ---------------- GCN gather (fp16, warp per node) -> fp16 agg -------------------
__global__ void gcn_gather_kernel() {
    int gw = (blockIdx.x * blockDim.x + threadIdx.x) >> 5;
    int lane = threadIdx.x & 31;
    if (gw >= N_NODES) return;
    int beg = g_rowptr[gw], end = g_rowptr[gw + 1];
    float dd = g_dinv[gw];

    float acc[3][8] = {};
    int valid[3];
    #pragma unroll
    for (int j = 0; j < 3; j++) valid[j] = (lane + 32 * j) < XTS / 8;

    for (int i = beg; i < end; i++) {
        int src = g_csr_src[i];
        float nm = dd * g_dinv[src];
        const float4* hs = (const float4*)(g_h1h + (long)src * XTS);
        #pragma unroll
        for (int j = 0; j < 3; j++) {
            if (!valid[j]) continue;
            float4 raw = hs[lane + 32 * j];
            const __half2* hp = (const __half2*)&raw;
            #pragma unroll
            for (int k = 0; k < 4; k++) {
                float2 v = __half22float2(hp[k]);
                acc[j][2 * k + 0] += v.x * nm;
                acc[j][2 * k + 1] += v.y * nm;
            }
        }
    }

    __half* hr = g_aah + (long)gw * KP_AGG;
    #pragma unroll
    for (int j = 0; j < 3; j++) {
        if (!valid[j]) continue;
        int f0 = (lane + 32 * j) * 8;
        __half2 o[4];
        #pragma unroll
        for (int k = 0; k < 8; k++)
            ((__half*)o)[k] = __float2half_rn(acc[j][k]);
        *(float4*)(hr + f0) = *(float4*)o;
    }
}

// ---------------- tail: sums split-K halves, applies g2 bias + leaky --------------
__global__ void tail_kernel(const float* __restrict__ W1, const float* __restrict__ b1,
                            const float* __restrict__ W2, const float* __restrict__ b2,
                            const float* __restrict__ W3, const float* __restrict__ b3,
                            const float* __restrict__ bg2,
                            float* __restrict__ out) {
    int gw = (blockIdx.x * blockDim.x + threadIdx.x) >> 5;
    int lane = threadIdx.x & 31;
    if (gw >= N_NODES) return;
    float v0 = leaky(g_h4a[gw * 64 + lane] + g_h4b[gw * 64 + lane] + bg2[lane], 0.01f);
    float v1 = leaky(g_h4a[gw * 64 + 32 + lane] + g_h4b[gw * 64 + 32 + lane] + bg2[32 + lane], 0.01f);
    float s = b1[lane];
    #pragma unroll
    for (int k = 0; k < 32; k++) s += __shfl_sync(0xffffffffu, v0, k) * W1[k * 32 + lane];
    #pragma unroll
    for (int k = 0; k < 32; k++) s += __shfl_sync(0xffffffffu, v1, k) * W1[(k + 32) * 32 + lane];
    float u = leaky(s, 0.01f);
    int j = lane & 15;
    float s2 = b2[j];
    #pragma unroll
    for (int k = 0; k < 32; k++) s2 += __shfl_sync(0xffffffffu, u, k) * W2[k * 16 + j];
    float t = leaky(s2, 0.01f);
    float o = (lane < 16) ? t * W3[lane] : 0.f;
    #pragma unroll
    for (int off = 8; off > 0; off >>= 1) o += __shfl_down_sync(0xffffffffu, o, off);
    if (lane == 0) out[gw] = o + b3[0];
}

// ---------------- launch --------------------------------------------------------------
extern "C" void kernel_launch(void* const* d_in, const int* in_sizes, int n_in,
                              void* d_out, int out_size) {
    const float* x     = (const float*)d_in[0];
    const int*   ei    = (const int*)  d_in[1];
    const float* W_gat = (const float*)d_in[2];
    const float* att_s = (const float*)d_in[3];
    const float* att_d = (const float*)d_in[4];
    const float* b_gat = (const float*)d_in[5];
    const float* W_gcn = (const float*)d_in[6];
    const float* b_gcn = (const float*)d_in[7];
    const float* W_g1  = (const float*)d_in[8];
    const float* b_g1  = (const float*)d_in[9];
    const float* W_g2  = (const float*)d_in[10];
    const float* b_g2  = (const float*)d_in[11];
    const float* W_fc1 = (const float*)d_in[12];
    const float* b_fc1 = (const float*)d_in[13];
    const float* W_fc2 = (const float*)d_in[14];
    const float* b_fc2 = (const float*)d_in[15];
    const float* W_out = (const float*)d_in[16];
    const float* b_out = (const float*)d_in[17];
    float* out = (float*)d_out;
    (void)in_sizes; (void)n_in; (void)out_size;

    cudaFuncSetAttribute(mma_gemm<false, false, true>, cudaFuncAttributeMaxDynamicSharedMemorySize, GEMM_SMEM);
    cudaFuncSetAttribute(mma_gemm<true, true, true>,   cudaFuncAttributeMaxDynamicSharedMemorySize, GEMM_SMEM);
    cudaFuncSetAttribute(mma_gemm<false, false, false>, cudaFuncAttributeMaxDynamicSharedMemorySize, GEMM_SMEM);

    float *p_h4a, *p_h4b;
    cudaGetSymbolAddress((void**)&p_h4a, g_h4a);
    cudaGetSymbolAddress((void**)&p_h4b, g_h4b);
    #define HADDR(p, s) __half* p; cudaGetSymbolAddress((void**)&p, s)
    HADDR(axh, g_axh); HADDR(aah, g_aah);
    HADDR(a2h, g_a2h); HADDR(a3h, g_a3h);
    HADDR(bgat, g_bgat); HADDR(bgcn, g_bgcn);
    HADDR(bg1, g_bg1); HADDR(bg2, g_bg2);
    HADDR(xth, g_xth);

    // fork: side stream handles CSR + attn precompute + non-critical converts
    cudaStream_t s2;
    cudaStreamCreateWithFlags(&s2, cudaStreamNonBlocking);
    cudaEvent_t e_fork, e_join;
    cudaEventCreateWithFlags(&e_fork, cudaEventDisableTiming);
    cudaEventCreateWithFlags(&e_join, cudaEventDisableTiming);

    cudaEventRecord(e_fork, 0);
    cudaStreamWaitEvent(s2, e_fork, 0);

    // side chain (independent of GAT GEMM)
    zero_small_kernel<<<(N_NODES + 255) / 256, 256, 0, s2>>>();
    deg_kernel<<<(E_TOT + 255) / 256, 256, 0, s2>>>(ei);
    scan_kernel<<<1, 1024, 0, s2>>>();
    fill_kernel<<<(E_TOT + 255) / 256, 256, 0, s2>>>(ei);
    ws_kernel<<<(HEADS * F_IN + 255) / 256, 256, 0, s2>>>(W_gat, att_s, att_d);
    asd_kernel<<<(N_NODES * HEADS + 255) / 256, 256, 0, s2>>>(x);
    cvt_rest_kernel<<<(CVT_REST + 255) / 256, 256, 0, s2>>>(W_gcn, W_g1, W_g2);

    // main chain: critical converts -> GAT GEMM
    cvt_crit_kernel<<<(CVT_CRIT + 255) / 256, 256>>>(x, W_gat);
    mma_gemm<false, false, true><<<dim3(NP_GAT / 128, M_PAD / 128), 256, GEMM_SMEM>>>(
        axh, bgat, nullptr, nullptr, nullptr, xth, KP_X, KP_X / 32, D1, XTS);

    // join
    cudaEventRecord(e_join, s2);
    cudaStreamWaitEvent(0, e_join, 0);

    gat_gather_kernel<<<(N_NODES * 32 + 255) / 256, 256>>>(b_gat);
    gcn_gather_kernel<<<(N_NODES * 32 + 255) / 256, 256>>>();

    // GCN linear -> fp16
    mma_gemm<true, true, true><<<dim3(NP_GCN / 128, M_PAD / 128), 256, GEMM_SMEM>>>(
        aah, bgcn, b_gcn, nullptr, nullptr, a2h, KP_AGG, KP_AGG / 32, D2, KP_H2);
    // g1 -> fp16
    mma_gemm<true, true, true><<<dim3(NP_G1 / 128, M_PAD / 128), 256, GEMM_SMEM>>>(
        a2h, bg1, b_g1, nullptr, nullptr, a3h, KP_H2, KP_H2 / 32, D3, KP_H3);
    // g2 split-K (z=2)
    mma_gemm<false, false, false><<<dim3(NP_G2 / 128, M_PAD / 128, 2), 256, GEMM_SMEM>>>(
        a3h, bg2, nullptr, p_h4a, p_h4b, nullptr, KP_H3, KP_H3 / 64, D4, D4);

    tail_kernel<<<(N_NODES * 32 + 255) / 256, 256>>>(
        W_fc1, b_fc1, W_fc2, b_fc2, W_out, b_out, b_g2, out);

    cudaEventDestroy(e_fork);
    cudaEventDestroy(e_join);
    cudaStreamDestroy(s2);
}

// round 11
// speedup vs baseline: 1.3141x; 1.0407x over previous
#include <cuda_runtime.h>
#include <cuda_fp16.h>
#include <math.h>
#include <stdint.h>

#define N_NODES 10000
#define N_EDGES 120000
#define E_TOT   130000
#define F_IN    66
#define HEADS   10
#define FHEAD   66
#define D1      660
#define D2      1320
#define D3      1000
#define D4      64
#define M_PAD   10112        // 79 * 128

#define KP_X    96
#define KP_AGG  672
#define KP_H2   1344
#define KP_H3   1024
#define NP_GAT  768
#define NP_GCN  1408
#define NP_G1   1024
#define NP_G2   128
#define XTS     672          // fp16 row stride for xt / h1

// ---------------- scratch ------------------------------------------------------
__device__             float g_as [N_NODES * HEADS];
__device__             float g_ad [N_NODES * HEADS];
__device__             float g_ws [HEADS * F_IN];
__device__             float g_wd [HEADS * F_IN];
__device__             float g_dinv[N_NODES];
__device__ __align__(16) float g_h4a[N_NODES * D4];
__device__ __align__(16) float g_h4b[N_NODES * D4];

__device__ __align__(16) __half g_xth [N_NODES * XTS];
__device__ __align__(16) __half g_h1h [N_NODES * XTS];

// ---------------- CSR over destination ------------------------------------------
__device__ int g_deg_i [N_NODES];
__device__ int g_fill  [N_NODES];
__device__ int g_rowptr[N_NODES + 1];
__device__ int g_csr_src[E_TOT];

// ---------------- fp16 GEMM buffers ----------------------------------------------
__device__ __align__(16) __half g_axh [M_PAD * KP_X];
__device__ __align__(16) __half g_aah [M_PAD * KP_AGG];
__device__ __align__(16) __half g_a2h [M_PAD * KP_H2];
__device__ __align__(16) __half g_a3h [M_PAD * KP_H3];
__device__ __align__(16) __half g_bgat[NP_GAT * KP_X];
__device__ __align__(16) __half g_bgcn[NP_GCN * KP_AGG];
__device__ __align__(16) __half g_bg1 [NP_G1 * KP_H2];
__device__ __align__(16) __half g_bg2 [NP_G2 * KP_H3];

// ---------------- baseline-PTX helpers -------------------------------------------
__device__ __forceinline__ uint32_t smem_u32(const void* p) {
    uint32_t a;
    asm("{ .reg .u64 t; cvta.to.shared.u64 t, %1; cvt.u32.u64 %0, t; }" : "=r"(a) : "l"(p));
    return a;
}
__device__ __forceinline__ void cp16(uint32_t dst, const void* src) {
    asm volatile("cp.async.cg.shared.global [%0], [%1], 16;" :: "r"(dst), "l"(src));
}
__device__ __forceinline__ void cp_commit() { asm volatile("cp.async.commit_group;"); }
template<int N> __device__ __forceinline__ void cp_wait() {
    asm volatile("cp.async.wait_group %0;" :: "n"(N));
}
__device__ __forceinline__ void ldsm4(uint32_t* r, uint32_t addr) {
    asm volatile("ldmatrix.sync.aligned.m8n8.x4.shared.b16 {%0,%1,%2,%3}, [%4];"
        : "=r"(r[0]), "=r"(r[1]), "=r"(r[2]), "=r"(r[3]) : "r"(addr));
}
__device__ __forceinline__ void mma_f16(float* d, const uint32_t* a, const uint32_t* b) {
    asm volatile("mma.sync.aligned.m16n8k16.row.col.f32.f16.f16.f32 "
        "{%0,%1,%2,%3}, {%4,%5,%6,%7}, {%8,%9}, {%0,%1,%2,%3};"
        : "+f"(d[0]), "+f"(d[1]), "+f"(d[2]), "+f"(d[3])
        : "r"(a[0]), "r"(a[1]), "r"(a[2]), "r"(a[3]), "r"(b[0]), "r"(b[1]));
}

// ---------------- misc ------------------------------------------------------------
__device__ __forceinline__ void edge_sd(const int* ei, int e, int& s, int& d) {
    if (e < N_EDGES) { s = ei[e]; d = ei[N_EDGES + e]; }
    else             { s = d = e - N_EDGES; }
}
__device__ __forceinline__ float leaky(float v, float sl) { return v >= 0.f ? v : sl * v; }

// ---------------- CSR build ---------------------------------------------------------
__global__ void zero_small_kernel() {
    int i = blockIdx.x * blockDim.x + threadIdx.x;
    if (i < N_NODES) { g_deg_i[i] = 0; g_fill[i] = 0; }
}
__global__ void deg_kernel(const int* __restrict__ ei) {
    int e = blockIdx.x * blockDim.x + threadIdx.x;
    if (e >= E_TOT) return;
    int s, d; edge_sd(ei, e, s, d);
    atomicAdd(&g_deg_i[d], 1);
}
__global__ void scan_kernel() {   // single block; also computes dinv
    __shared__ int sm[1024];
    int tid = threadIdx.x;
    int base = tid * 10;
    int local[10]; int sum = 0;
    #pragma unroll
    for (int i = 0; i < 10; i++) {
        int v = (base + i < N_NODES) ? g_deg_i[base + i] : 0;
        if (base + i < N_NODES) g_dinv[base + i] = rsqrtf(fmaxf((float)v, 1.f));
        local[i] = sum; sum += v;
    }
    sm[tid] = sum; __syncthreads();
    for (int off = 1; off < 1024; off <<= 1) {
        int v = (tid >= off) ? sm[tid - off] : 0;
        __syncthreads();
        sm[tid] += v;
        __syncthreads();
    }
    int pre = (tid > 0) ? sm[tid - 1] : 0;
    #pragma unroll
    for (int i = 0; i < 10; i++)
        if (base + i < N_NODES) g_rowptr[base + i] = pre + local[i];
    if (tid == 1023) g_rowptr[N_NODES] = sm[1023];
}
__global__ void fill_kernel(const int* __restrict__ ei) {
    int e = blockIdx.x * blockDim.x + threadIdx.x;
    if (e >= E_TOT) return;
    int s, d; edge_sd(ei, e, s, d);
    int pos = atomicAdd(&g_fill[d], 1);
    g_csr_src[g_rowptr[d] + pos] = s;
}

// ---------------- attn hoist: w = W_gat @ att (per head), then a = x @ w ------------
__global__ void ws_kernel(const float* __restrict__ Wgat,
                          const float* __restrict__ att_s, const float* __restrict__ att_d) {
    int idx = blockIdx.x * blockDim.x + threadIdx.x;
    if (idx >= HEADS * F_IN) return;
    int h = idx / F_IN, i = idx - h * F_IN;
    const float* wrow = Wgat + (long)i * D1 + h * FHEAD;
    const float* as = att_s + h * FHEAD;
    const float* ad = att_d + h * FHEAD;
    float s = 0.f, d = 0.f;
    #pragma unroll
    for (int f = 0; f < FHEAD; f++) { float w = wrow[f]; s += w * as[f]; d += w * ad[f]; }
    g_ws[idx] = s; g_wd[idx] = d;
}
__global__ void asd_kernel(const float* __restrict__ x) {
    int idx = blockIdx.x * blockDim.x + threadIdx.x;
    if (idx >= N_NODES * HEADS) return;
    int n = idx / HEADS, h = idx - n * HEADS;
    const float* xr = x + (long)n * F_IN;
    const float* ws = g_ws + h * F_IN;
    const float* wd = g_wd + h * F_IN;
    float s = 0.f, d = 0.f;
    #pragma unroll
    for (int i = 0; i < F_IN; i++) { float v = xr[i]; s += v * ws[i]; d += v * wd[i]; }
    g_as[idx] = s; g_ad[idx] = d;
}

// ---------------- converts: critical (axh,bgat) and rest (bgcn,bg1,bg2) --------------
#define R0 (NP_GAT * KP_X)
#define R4 (M_PAD * KP_X)
#define CVT_CRIT (R0 + R4)
#define R1 (NP_GCN * KP_AGG)
#define R2 (NP_G1 * KP_H2)
#define R3 (NP_G2 * KP_H3)
#define CVT_REST (R1 + R2 + R3)

__device__ __forceinline__ void cvtB_one(const float* W, __half* dst, int idx,
                                         int K, int Nn, int Kp) {
    int n = idx / Kp, k = idx - n * Kp;
    float v = (k < K && n < Nn) ? W[(long)k * Nn + n] : 0.f;
    dst[idx] = __float2half_rn(v);
}
__global__ void cvt_crit_kernel(const float* __restrict__ x, const float* __restrict__ Wgat) {
    int idx = blockIdx.x * blockDim.x + threadIdx.x;
    if (idx >= CVT_CRIT) return;
    if (idx < R0) { cvtB_one(Wgat, g_bgat, idx, F_IN, D1, KP_X); return; }
    idx -= R0;
    int r = idx / KP_X, c = idx - r * KP_X;
    float v = (r < N_NODES && c < F_IN) ? x[(long)r * F_IN + c] : 0.f;
    g_axh[idx] = __float2half_rn(v);
}
__global__ void cvt_rest_kernel(const float* __restrict__ Wgcn,
                                const float* __restrict__ Wg1, const float* __restrict__ Wg2) {
    int idx = blockIdx.x * blockDim.x + threadIdx.x;
    if (idx >= CVT_REST) return;
    if (idx < R1) { cvtB_one(Wgcn, g_bgcn, idx, D1, D2, KP_AGG); return; }
    idx -= R1;
    if (idx < R2) { cvtB_one(Wg1, g_bg1, idx, D2, D3, KP_H2); return; }
    idx -= R2;
    cvtB_one(Wg2, g_bg2, idx, D3, D4, KP_H3);
}

// ---------------- HMMA GEMM (single fp16, 4-stage cp.async, 2 CTAs/SM) ----------------
#define TSTRIDE  80
#define B_HI_OFF 10240
#define STAGE_SZ 20480
#define GEMM_SMEM (4 * STAGE_SZ)

__device__ __forceinline__ void fill_stage(uint32_t st,
        const __half* __restrict__ A, const __half* __restrict__ B,
        int m0, int n0, int Kp, int k0, int tid) {
    #pragma unroll
    for (int i = 0; i < 2; i++) {
        int lin = tid + i * 256;
        int r = lin >> 2, cc = lin & 3;
        uint32_t d = st + r * TSTRIDE + cc * 16;
        cp16(d,            (const char*)(A + (long)(m0 + r) * Kp + k0) + cc * 16);
        cp16(d + B_HI_OFF, (const char*)(B + (long)(n0 + r) * Kp + k0) + cc * 16);
    }
    cp_commit();
}

template<bool BIAS, bool ACT, bool SPLIT>
__global__ __launch_bounds__(256, 2)
void mma_gemm(const __half* __restrict__ Ah, const __half* __restrict__ Bh,
              const float* __restrict__ bias, float* __restrict__ C,
              float* __restrict__ C2, __half* __restrict__ Sh,
              int Kp, int chunks, int Nreal, int ldC) {
    extern __shared__ char smem[];
    const uint32_t tile0 = smem_u32(smem);
    const int tid = threadIdx.x, wid = tid >> 5, lane = tid & 31;
    const int m0 = blockIdx.y * 128, n0 = blockIdx.x * 128;
    const int kbase = blockIdx.z * chunks * 32;
    const int mwoff = (wid >> 1) * 32, nwoff = (wid & 1) * 64;

    const int mat = lane >> 3, mrow = lane & 7;
    uint32_t a_off[2], b_off[4];
    #pragma unroll
    for (int ti = 0; ti < 2; ti++)
        a_off[ti] = (uint32_t)((mwoff + ti * 16 + ((mat & 1) << 3) + mrow) * TSTRIDE
                               + (mat >> 1) * 16);
    #pragma unroll
    for (int nt = 0; nt < 4; nt++)
        b_off[nt] = (uint32_t)((nwoff + nt * 16 + ((mat >> 1) << 3) + mrow) * TSTRIDE
                               + (mat & 1) * 16);

    float acc[2][8][4] = {};

    fill_stage(tile0, Ah, Bh, m0, n0, Kp, kbase, tid);
    if (chunks > 1) fill_stage(tile0 + STAGE_SZ, Ah, Bh, m0, n0, Kp, kbase + 32, tid);
    if (chunks > 2) fill_stage(tile0 + 2 * STAGE_SZ, Ah, Bh, m0, n0, Kp, kbase + 64, tid);

    for (int c = 0; c < chunks; c++) {
        if (c + 2 < chunks)      cp_wait<2>();
        else if (c + 1 < chunks) cp_wait<1>();
        else                     cp_wait<0>();
        __syncthreads();
        if (c + 3 < chunks)
            fill_stage(tile0 + ((c + 3) & 3) * STAGE_SZ, Ah, Bh,
                       m0, n0, Kp, kbase + (c + 3) * 32, tid);
        uint32_t sb = tile0 + (c & 3) * STAGE_SZ;
        #pragma unroll
        for (int kh = 0; kh < 2; kh++) {
            uint32_t ah[2][4], bh[4][4];
            #pragma unroll
            for (int ti = 0; ti < 2; ti++)
                ldsm4(ah[ti], sb + a_off[ti] + kh * 32);
            #pragma unroll
            for (int nt = 0; nt < 4; nt++)
                ldsm4(bh[nt], sb + B_HI_OFF + b_off[nt] + kh * 32);
            #pragma unroll
            for (int ti = 0; ti < 2; ti++)
                #pragma unroll
                for (int nt = 0; nt < 8; nt++)
                    mma_f16(acc[ti][nt], ah[ti], &bh[nt >> 1][(nt & 1) * 2]);
        }
    }

    float* Cout = (blockIdx.z == 0) ? C : C2;
    const int lr = lane >> 2, lc = (lane & 3) * 2;
    #pragma unroll
    for (int ti = 0; ti < 2; ti++)
        #pragma unroll
        for (int rp = 0; rp < 2; rp++) {
            int gr = m0 + mwoff + ti * 16 + rp * 8 + lr;
            if (gr >= N_NODES) continue;
            if (!SPLIT) {
                float* crow = Cout + (long)gr * ldC;
                #pragma unroll
                for (int nt = 0; nt < 8; nt++) {
                    int gc = n0 + nwoff + nt * 8 + lc;
                    float v0 = acc[ti][nt][rp * 2 + 0];
                    float v1 = acc[ti][nt][rp * 2 + 1];
                    if (gc < Nreal) {
                        if (BIAS) v0 += bias[gc];
                        if (ACT)  v0 = leaky(v0, 0.01f);
                        crow[gc] = v0;
                    }
                    if (gc + 1 < Nreal) {
                        if (BIAS) v1 += bias[gc + 1];
                        if (ACT)  v1 = leaky(v1, 0.01f);
                        crow[gc + 1] = v1;
                    }
                }
            } else {
                __half* hr = Sh + (long)gr * ldC;
                #pragma unroll
                for (int nt = 0; nt < 8; nt++) {
                    int gc = n0 + nwoff + nt * 8 + lc;
                    if (gc >= ldC) continue;
                    float v0 = 0.f, v1 = 0.f;
                    if (gc < Nreal) {
                        v0 = acc[ti][nt][rp * 2 + 0];
                        if (BIAS) v0 += bias[gc];
                        if (ACT)  v0 = leaky(v0, 0.01f);
                    }
                    if (gc + 1 < Nreal) {
                        v1 = acc[ti][nt][rp * 2 + 1];
                        if (BIAS) v1 += bias[gc + 1];
                        if (ACT)  v1 = leaky(v1, 0.01f);
                    }
                    __half2 hp;
                    hp.x = __float2half_rn(v0);
                    hp.y = __float2half_rn(v1);
                    *(__half2*)(hr + gc) = hp;
                }
            }
        }
}

// ---------------- GAT gather: SINGLE PASS (normalize at end) ---------------------
__global__ void gat_gather_kernel(const float* __restrict__ b_gat) {
    int gw = (blockIdx.x * blockDim.x + threadIdx.x) >> 5;
    int lane = threadIdx.x & 31;
    int wl = threadIdx.x >> 5;
    __shared__ float sal[8][12];
    if (gw >= N_NODES) return;
    int beg = g_rowptr[gw], end = g_rowptr[gw + 1];

    float adl = (lane < HEADS) ? g_ad[gw * HEADS + lane] : 0.f;

    int h0[3], pos[3], valid[3];
    #pragma unroll
    for (int j = 0; j < 3; j++) {
        int f4 = lane + 32 * j;
        valid[j] = (f4 < XTS / 8);
        int f0 = f4 * 8;
        int hh = f0 / FHEAD; if (hh > 9) hh = 9;
        h0[j] = hh;
        pos[j] = (hh + 1) * FHEAD - f0;
    }

    float acc[3][8] = {};
    float ssum = 0.f;   // per-head sum of weights (lanes 0..9)

    for (int i = beg; i < end; i++) {
        int src = g_csr_src[i];
        if (lane < 12) {
            float w = (lane < HEADS)
                ? expf(leaky(g_as[src * HEADS + lane] + adl, 0.2f)) : 0.f;
            sal[wl][lane] = w;
            ssum += w;
        }
        __syncwarp();
        const float4* xs = (const float4*)(g_xth + (long)src * XTS);
        #pragma unroll
        for (int j = 0; j < 3; j++) {
            if (!valid[j]) continue;
            float4 raw = xs[lane + 32 * j];
            const __half2* hp = (const __half2*)&raw;
            float s0 = sal[wl][h0[j]], s1 = sal[wl][h0[j] + 1];
            #pragma unroll
            for (int k = 0; k < 4; k++) {
                float2 v = __half22float2(hp[k]);
                acc[j][2 * k + 0] += v.x * (2 * k     < pos[j] ? s0 : s1);
                acc[j][2 * k + 1] += v.y * (2 * k + 1 < pos[j] ? s0 : s1);
            }
        }
        __syncwarp();
    }

    // publish 1/ssum per head, then normalize in epilogue
    if (lane < 12)
        sal[wl][lane] = (lane < HEADS) ? 1.f / fmaxf(ssum, 1e-16f) : 0.f;
    __syncwarp();

    __half* hd = g_h1h + (long)gw * XTS;
    #pragma unroll
    for (int j = 0; j < 3; j++) {
        if (!valid[j]) continue;
        int f0 = (lane + 32 * j) * 8;
        float i0 = sal[wl][h0[j]], i1 = sal[wl][h0[j] + 1];
        __half2 o[4];
        #pragma unroll
        for (int k = 0; k < 8; k++) {
            int f = f0 + k;
            float inv = (k < pos[j]) ? i0 : i1;
            float v = (f < D1) ? leaky(acc[j][k] * inv + b_gat[f], 0.01f) : 0.f;
            ((__half*)o)[k] = __float2half_rn(v);
        }
        *(float4*)(hd + f0) = *(float4*)o;
    }
}

// ---------------- GCN gather (fp16, warp per node) -> fp16 agg -------------------
__global__ void gcn_gather_kernel() {
    int gw = (blockIdx.x * blockDim.x + threadIdx.x) >> 5;
    int lane = threadIdx.x & 31;
    if (gw >= N_NODES) return;
    int beg = g_rowptr[gw], end = g_rowptr[gw + 1];
    float dd = g_dinv[gw];

    float acc[3][8] = {};
    int valid[3];
    #pragma unroll
    for (int j = 0; j < 3; j++) valid[j] = (lane + 32 * j) < XTS / 8;

    for (int i = beg; i < end; i++) {
        int src = g_csr_src[i];
        float nm = dd * g_dinv[src];
        const float4* hs = (const float4*)(g_h1h + (long)src * XTS);
        #pragma unroll
        for (int j = 0; j < 3; j++) {
            if (!valid[j]) continue;
            float4 raw = hs[lane + 32 * j];
            const __half2* hp = (const __half2*)&raw;
            #pragma unroll
            for (int k = 0; k < 4; k++) {
                float2 v = __half22float2(hp[k]);
                acc[j][2 * k + 0] += v.x * nm;
                acc[j][2 * k + 1] += v.y * nm;
            }
        }
    }

    __half* hr = g_aah + (long)gw * KP_AGG;
    #pragma unroll
    for (int j = 0; j < 3; j++) {
        if (!valid[j]) continue;
        int f0 = (lane + 32 * j) * 8;
        __half2 o[4];
        #pragma unroll
        for (int k = 0; k < 8; k++)
            ((__half*)o)[k] = __float2half_rn(acc[j][k]);
        *(float4*)(hr + f0) = *(float4*)o;
    }
}

// ---------------- tail: sums split-K halves, applies g2 bias + leaky --------------
__global__ void tail_kernel(const float* __restrict__ W1, const float* __restrict__ b1,
                            const float* __restrict__ W2, const float* __restrict__ b2,
                            const float* __restrict__ W3, const float* __restrict__ b3,
                            const float* __restrict__ bg2,
                            float* __restrict__ out) {
    int gw = (blockIdx.x * blockDim.x + threadIdx.x) >> 5;
    int lane = threadIdx.x & 31;
    if (gw >= N_NODES) return;
    float v0 = leaky(g_h4a[gw * 64 + lane] + g_h4b[gw * 64 + lane] + bg2[lane], 0.01f);
    float v1 = leaky(g_h4a[gw * 64 + 32 + lane] + g_h4b[gw * 64 + 32 + lane] + bg2[32 + lane], 0.01f);
    float s = b1[lane];
    #pragma unroll
    for (int k = 0; k < 32; k++) s += __shfl_sync(0xffffffffu, v0, k) * W1[k * 32 + lane];
    #pragma unroll
    for (int k = 0; k < 32; k++) s += __shfl_sync(0xffffffffu, v1, k) * W1[(k + 32) * 32 + lane];
    float u = leaky(s, 0.01f);
    int j = lane & 15;
    float s2 = b2[j];
    #pragma unroll
    for (int k = 0; k < 32; k++) s2 += __shfl_sync(0xffffffffu, u, k) * W2[k * 16 + j];
    float t = leaky(s2, 0.01f);
    float o = (lane < 16) ? t * W3[lane] : 0.f;
    #pragma unroll
    for (int off = 8; off > 0; off >>= 1) o += __shfl_down_sync(0xffffffffu, o, off);
    if (lane == 0) out[gw] = o + b3[0];
}

// ---------------- launch --------------------------------------------------------------
extern "C" void kernel_launch(void* const* d_in, const int* in_sizes, int n_in,
                              void* d_out, int out_size) {
    const float* x     = (const float*)d_in[0];
    const int*   ei    = (const int*)  d_in[1];
    const float* W_gat = (const float*)d_in[2];
    const float* att_s = (const float*)d_in[3];
    const float* att_d = (const float*)d_in[4];
    const float* b_gat = (const float*)d_in[5];
    const float* W_gcn = (const float*)d_in[6];
    const float* b_gcn = (const float*)d_in[7];
    const float* W_g1  = (const float*)d_in[8];
    const float* b_g1  = (const float*)d_in[9];
    const float* W_g2  = (const float*)d_in[10];
    const float* b_g2  = (const float*)d_in[11];
    const float* W_fc1 = (const float*)d_in[12];
    const float* b_fc1 = (const float*)d_in[13];
    const float* W_fc2 = (const float*)d_in[14];
    const float* b_fc2 = (const float*)d_in[15];
    const float* W_out = (const float*)d_in[16];
    const float* b_out = (const float*)d_in[17];
    float* out = (float*)d_out;
    (void)in_sizes; (void)n_in; (void)out_size;

    cudaFuncSetAttribute(mma_gemm<false, false, true>, cudaFuncAttributeMaxDynamicSharedMemorySize, GEMM_SMEM);
    cudaFuncSetAttribute(mma_gemm<true, true, true>,   cudaFuncAttributeMaxDynamicSharedMemorySize, GEMM_SMEM);
    cudaFuncSetAttribute(mma_gemm<false, false, false>, cudaFuncAttributeMaxDynamicSharedMemorySize, GEMM_SMEM);

    float *p_h4a, *p_h4b;
    cudaGetSymbolAddress((void**)&p_h4a, g_h4a);
    cudaGetSymbolAddress((void**)&p_h4b, g_h4b);
    #define HADDR(p, s) __half* p; cudaGetSymbolAddress((void**)&p, s)
    HADDR(axh, g_axh); HADDR(aah, g_aah);
    HADDR(a2h, g_a2h); HADDR(a3h, g_a3h);
    HADDR(bgat, g_bgat); HADDR(bgcn, g_bgcn);
    HADDR(bg1, g_bg1); HADDR(bg2, g_bg2);
    HADDR(xth, g_xth);

    // three-way fork: s2 = CSR chain (+deferred cvt_rest), s3 = attn precompute
    cudaStream_t s2, s3;
    cudaStreamCreateWithFlags(&s2, cudaStreamNonBlocking);
    cudaStreamCreateWithFlags(&s3, cudaStreamNonBlocking);
    cudaEvent_t e_fork, e_csr, e_asd, e_cvt;
    cudaEventCreateWithFlags(&e_fork, cudaEventDisableTiming);
    cudaEventCreateWithFlags(&e_csr,  cudaEventDisableTiming);
    cudaEventCreateWithFlags(&e_asd,  cudaEventDisableTiming);
    cudaEventCreateWithFlags(&e_cvt,  cudaEventDisableTiming);

    cudaEventRecord(e_fork, 0);
    cudaStreamWaitEvent(s2, e_fork, 0);
    cudaStreamWaitEvent(s3, e_fork, 0);

    // s2: CSR chain, then non-critical converts (only needed by GCN GEMM)
    zero_small_kernel<<<(N_NODES + 255) / 256, 256, 0, s2>>>();
    deg_kernel<<<(E_TOT + 255) / 256, 256, 0, s2>>>(ei);
    scan_kernel<<<1, 1024, 0, s2>>>();
    fill_kernel<<<(E_TOT + 255) / 256, 256, 0, s2>>>(ei);
    cudaEventRecord(e_csr, s2);
    cvt_rest_kernel<<<(CVT_REST + 255) / 256, 256, 0, s2>>>(W_gcn, W_g1, W_g2);
    cudaEventRecord(e_cvt, s2);

    // s3: attention coefficients (independent of GAT GEMM)
    ws_kernel<<<(HEADS * F_IN + 255) / 256, 256, 0, s3>>>(W_gat, att_s, att_d);
    asd_kernel<<<(N_NODES * HEADS + 255) / 256, 256, 0, s3>>>(x);
    cudaEventRecord(e_asd, s3);

    // main: critical converts -> GAT GEMM
    cvt_crit_kernel<<<(CVT_CRIT + 255) / 256, 256>>>(x, W_gat);
    mma_gemm<false, false, true><<<dim3(NP_GAT / 128, M_PAD / 128), 256, GEMM_SMEM>>>(
        axh, bgat, nullptr, nullptr, nullptr, xth, KP_X, KP_X / 32, D1, XTS);

    // join CSR + asd before gathers
    cudaStreamWaitEvent(0, e_csr, 0);
    cudaStreamWaitEvent(0, e_asd, 0);

    gat_gather_kernel<<<(N_NODES * 32 + 255) / 256, 256>>>(b_gat);
    gcn_gather_kernel<<<(N_NODES * 32 + 255) / 256, 256>>>();

    // join converts just before GCN GEMM (overlaps with the gathers)
    cudaStreamWaitEvent(0, e_cvt, 0);

    mma_gemm<true, true, true><<<dim3(NP_GCN / 128, M_PAD / 128), 256, GEMM_SMEM>>>(
        aah, bgcn, b_gcn, nullptr, nullptr, a2h, KP_AGG, KP_AGG / 32, D2, KP_H2);
    mma_gemm<true, true, true><<<dim3(NP_G1 / 128, M_PAD / 128), 256, GEMM_SMEM>>>(
        a2h, bg1, b_g1, nullptr, nullptr, a3h, KP_H2, KP_H2 / 32, D3, KP_H3);
    mma_gemm<false, false, false><<<dim3(NP_G2 / 128, M_PAD / 128, 2), 256, GEMM_SMEM>>>(
        a3h, bg2, nullptr, p_h4a, p_h4b, nullptr, KP_H3, KP_H3 / 64, D4, D4);

    tail_kernel<<<(N_NODES * 32 + 255) / 256, 256>>>(
        W_fc1, b_fc1, W_fc2, b_fc2, W_out, b_out, b_g2, out);

    cudaEventDestroy(e_fork);
    cudaEventDestroy(e_csr);
    cudaEventDestroy(e_asd);
    cudaEventDestroy(e_cvt);
    cudaStreamDestroy(s2);
    cudaStreamDestroy(s3);
}

// round 12
// speedup vs baseline: 1.4199x; 1.0805x over previous
#include <cuda_runtime.h>
#include <cuda_fp16.h>
#include <math.h>
#include <stdint.h>

#define N_NODES 10000
#define N_EDGES 120000
#define E_TOT   130000
#define F_IN    66
#define HEADS   10
#define FHEAD   66
#define D1      660
#define D2      1320
#define D3      1000
#define D4      64
#define M_PAD   10112        // 79 * 128

#define KP_X    96
#define KP_AGG  672
#define KP_H2   1344
#define KP_H3   1024
#define NP_GAT  768
#define NP_GCN  1408
#define NP_G1   1024
#define NP_G2   128
#define XTS     672

// M-half split (multiples of 128)
#define MSPLIT_NODE 5120
#define MBLK0 40
#define MBLK1 39

// ---------------- scratch ------------------------------------------------------
__device__             float g_as [N_NODES * HEADS];
__device__             float g_ad [N_NODES * HEADS];
__device__             float g_ws [HEADS * F_IN];
__device__             float g_wd [HEADS * F_IN];
__device__             float g_dinv[N_NODES];
__device__ __align__(16) float g_h4a[N_NODES * D4];
__device__ __align__(16) float g_h4b[N_NODES * D4];

__device__ __align__(16) __half g_xth [N_NODES * XTS];
__device__ __align__(16) __half g_h1h [N_NODES * XTS];

// ---------------- CSR over destination ------------------------------------------
__device__ int g_deg_i [N_NODES];
__device__ int g_fill  [N_NODES];
__device__ int g_rowptr[N_NODES + 1];
__device__ int g_csr_src[E_TOT];

// ---------------- fp16 GEMM buffers ----------------------------------------------
__device__ __align__(16) __half g_axh [M_PAD * KP_X];
__device__ __align__(16) __half g_aah [M_PAD * KP_AGG];
__device__ __align__(16) __half g_a2h [M_PAD * KP_H2];
__device__ __align__(16) __half g_a3h [M_PAD * KP_H3];
__device__ __align__(16) __half g_bgat[NP_GAT * KP_X];
__device__ __align__(16) __half g_bgcn[NP_GCN * KP_AGG];
__device__ __align__(16) __half g_bg1 [NP_G1 * KP_H2];
__device__ __align__(16) __half g_bg2 [NP_G2 * KP_H3];

// ---------------- baseline-PTX helpers -------------------------------------------
__device__ __forceinline__ uint32_t smem_u32(const void* p) {
    uint32_t a;
    asm("{ .reg .u64 t; cvta.to.shared.u64 t, %1; cvt.u32.u64 %0, t; }" : "=r"(a) : "l"(p));
    return a;
}
__device__ __forceinline__ void cp16(uint32_t dst, const void* src) {
    asm volatile("cp.async.cg.shared.global [%0], [%1], 16;" :: "r"(dst), "l"(src));
}
__device__ __forceinline__ void cp_commit() { asm volatile("cp.async.commit_group;"); }
template<int N> __device__ __forceinline__ void cp_wait() {
    asm volatile("cp.async.wait_group %0;" :: "n"(N));
}
__device__ __forceinline__ void ldsm4(uint32_t* r, uint32_t addr) {
    asm volatile("ldmatrix.sync.aligned.m8n8.x4.shared.b16 {%0,%1,%2,%3}, [%4];"
        : "=r"(r[0]), "=r"(r[1]), "=r"(r[2]), "=r"(r[3]) : "r"(addr));
}
__device__ __forceinline__ void mma_f16(float* d, const uint32_t* a, const uint32_t* b) {
    asm volatile("mma.sync.aligned.m16n8k16.row.col.f32.f16.f16.f32 "
        "{%0,%1,%2,%3}, {%4,%5,%6,%7}, {%8,%9}, {%0,%1,%2,%3};"
        : "+f"(d[0]), "+f"(d[1]), "+f"(d[2]), "+f"(d[3])
        : "r"(a[0]), "r"(a[1]), "r"(a[2]), "r"(a[3]), "r"(b[0]), "r"(b[1]));
}

// ---------------- misc ------------------------------------------------------------
__device__ __forceinline__ void edge_sd(const int* ei, int e, int& s, int& d) {
    if (e < N_EDGES) { s = ei[e]; d = ei[N_EDGES + e]; }
    else             { s = d = e - N_EDGES; }
}
__device__ __forceinline__ float leaky(float v, float sl) { return v >= 0.f ? v : sl * v; }

// ---------------- CSR build ---------------------------------------------------------
__global__ void zero_small_kernel() {
    int i = blockIdx.x * blockDim.x + threadIdx.x;
    if (i < N_NODES) { g_deg_i[i] = 0; g_fill[i] = 0; }
}
__global__ void deg_kernel(const int* __restrict__ ei) {
    int e = blockIdx.x * blockDim.x + threadIdx.x;
    if (e >= E_TOT) return;
    int s, d; edge_sd(ei, e, s, d);
    atomicAdd(&g_deg_i[d], 1);
}
__global__ void scan_kernel() {
    __shared__ int sm[1024];
    int tid = threadIdx.x;
    int base = tid * 10;
    int local[10]; int sum = 0;
    #pragma unroll
    for (int i = 0; i < 10; i++) {
        int v = (base + i < N_NODES) ? g_deg_i[base + i] : 0;
        if (base + i < N_NODES) g_dinv[base + i] = rsqrtf(fmaxf((float)v, 1.f));
        local[i] = sum; sum += v;
    }
    sm[tid] = sum; __syncthreads();
    for (int off = 1; off < 1024; off <<= 1) {
        int v = (tid >= off) ? sm[tid - off] : 0;
        __syncthreads();
        sm[tid] += v;
        __syncthreads();
    }
    int pre = (tid > 0) ? sm[tid - 1] : 0;
    #pragma unroll
    for (int i = 0; i < 10; i++)
        if (base + i < N_NODES) g_rowptr[base + i] = pre + local[i];
    if (tid == 1023) g_rowptr[N_NODES] = sm[1023];
}
__global__ void fill_kernel(const int* __restrict__ ei) {
    int e = blockIdx.x * blockDim.x + threadIdx.x;
    if (e >= E_TOT) return;
    int s, d; edge_sd(ei, e, s, d);
    int pos = atomicAdd(&g_fill[d], 1);
    g_csr_src[g_rowptr[d] + pos] = s;
}

// ---------------- attn hoist --------------------------------------------------------
__global__ void ws_kernel(const float* __restrict__ Wgat,
                          const float* __restrict__ att_s, const float* __restrict__ att_d) {
    int idx = blockIdx.x * blockDim.x + threadIdx.x;
    if (idx >= HEADS * F_IN) return;
    int h = idx / F_IN, i = idx - h * F_IN;
    const float* wrow = Wgat + (long)i * D1 + h * FHEAD;
    const float* as = att_s + h * FHEAD;
    const float* ad = att_d + h * FHEAD;
    float s = 0.f, d = 0.f;
    #pragma unroll
    for (int f = 0; f < FHEAD; f++) { float w = wrow[f]; s += w * as[f]; d += w * ad[f]; }
    g_ws[idx] = s; g_wd[idx] = d;
}
__global__ void asd_kernel(const float* __restrict__ x) {
    int idx = blockIdx.x * blockDim.x + threadIdx.x;
    if (idx >= N_NODES * HEADS) return;
    int n = idx / HEADS, h = idx - n * HEADS;
    const float* xr = x + (long)n * F_IN;
    const float* ws = g_ws + h * F_IN;
    const float* wd = g_wd + h * F_IN;
    float s = 0.f, d = 0.f;
    #pragma unroll
    for (int i = 0; i < F_IN; i++) { float v = xr[i]; s += v * ws[i]; d += v * wd[i]; }
    g_as[idx] = s; g_ad[idx] = d;
}

// ---------------- converts ------------------------------------------------------------
#define R0 (NP_GAT * KP_X)
#define R4 (M_PAD * KP_X)
#define CVT_CRIT (R0 + R4)
#define R1 (NP_GCN * KP_AGG)
#define R2 (NP_G1 * KP_H2)
#define R3 (NP_G2 * KP_H3)
#define CVT_REST (R1 + R2 + R3)

__device__ __forceinline__ void cvtB_one(const float* W, __half* dst, int idx,
                                         int K, int Nn, int Kp) {
    int n = idx / Kp, k = idx - n * Kp;
    float v = (k < K && n < Nn) ? W[(long)k * Nn + n] : 0.f;
    dst[idx] = __float2half_rn(v);
}
__global__ void cvt_crit_kernel(const float* __restrict__ x, const float* __restrict__ Wgat) {
    int idx = blockIdx.x * blockDim.x + threadIdx.x;
    if (idx >= CVT_CRIT) return;
    if (idx < R0) { cvtB_one(Wgat, g_bgat, idx, F_IN, D1, KP_X); return; }
    idx -= R0;
    int r = idx / KP_X, c = idx - r * KP_X;
    float v = (r < N_NODES && c < F_IN) ? x[(long)r * F_IN + c] : 0.f;
    g_axh[idx] = __float2half_rn(v);
}
__global__ void cvt_rest_kernel(const float* __restrict__ Wgcn,
                                const float* __restrict__ Wg1, const float* __restrict__ Wg2) {
    int idx = blockIdx.x * blockDim.x + threadIdx.x;
    if (idx >= CVT_REST) return;
    if (idx < R1) { cvtB_one(Wgcn, g_bgcn, idx, D1, D2, KP_AGG); return; }
    idx -= R1;
    if (idx < R2) { cvtB_one(Wg1, g_bg1, idx, D2, D3, KP_H2); return; }
    idx -= R2;
    cvtB_one(Wg2, g_bg2, idx, D3, D4, KP_H3);
}

// ---------------- HMMA GEMM (fp16, 4-stage cp.async, 2 CTAs/SM, M offset) -------------
#define TSTRIDE  80
#define B_HI_OFF 10240
#define STAGE_SZ 20480
#define GEMM_SMEM (4 * STAGE_SZ)

__device__ __forceinline__ void fill_stage(uint32_t st,
        const __half* __restrict__ A, const __half* __restrict__ B,
        int m0, int n0, int Kp, int k0, int tid) {
    #pragma unroll
    for (int i = 0; i < 2; i++) {
        int lin = tid + i * 256;
        int r = lin >> 2, cc = lin & 3;
        uint32_t d = st + r * TSTRIDE + cc * 16;
        cp16(d,            (const char*)(A + (long)(m0 + r) * Kp + k0) + cc * 16);
        cp16(d + B_HI_OFF, (const char*)(B + (long)(n0 + r) * Kp + k0) + cc * 16);
    }
    cp_commit();
}

template<bool BIAS, bool ACT, bool SPLIT>
__global__ __launch_bounds__(256, 2)
void mma_gemm(const __half* __restrict__ Ah, const __half* __restrict__ Bh,
              const float* __restrict__ bias, float* __restrict__ C,
              float* __restrict__ C2, __half* __restrict__ Sh,
              int Kp, int chunks, int Nreal, int ldC, int mblk_off) {
    extern __shared__ char smem[];
    const uint32_t tile0 = smem_u32(smem);
    const int tid = threadIdx.x, wid = tid >> 5, lane = tid & 31;
    const int m0 = (blockIdx.y + mblk_off) * 128, n0 = blockIdx.x * 128;
    const int kbase = blockIdx.z * chunks * 32;
    const int mwoff = (wid >> 1) * 32, nwoff = (wid & 1) * 64;

    const int mat = lane >> 3, mrow = lane & 7;
    uint32_t a_off[2], b_off[4];
    #pragma unroll
    for (int ti = 0; ti < 2; ti++)
        a_off[ti] = (uint32_t)((mwoff + ti * 16 + ((mat & 1) << 3) + mrow) * TSTRIDE
                               + (mat >> 1) * 16);
    #pragma unroll
    for (int nt = 0; nt < 4; nt++)
        b_off[nt] = (uint32_t)((nwoff + nt * 16 + ((mat >> 1) << 3) + mrow) * TSTRIDE
                               + (mat & 1) * 16);

    float acc[2][8][4] = {};

    fill_stage(tile0, Ah, Bh, m0, n0, Kp, kbase, tid);
    if (chunks > 1) fill_stage(tile0 + STAGE_SZ, Ah, Bh, m0, n0, Kp, kbase + 32, tid);
    if (chunks > 2) fill_stage(tile0 + 2 * STAGE_SZ, Ah, Bh, m0, n0, Kp, kbase + 64, tid);

    for (int c = 0; c < chunks; c++) {
        if (c + 2 < chunks)      cp_wait<2>();
        else if (c + 1 < chunks) cp_wait<1>();
        else                     cp_wait<0>();
        __syncthreads();
        if (c + 3 < chunks)
            fill_stage(tile0 + ((c + 3) & 3) * STAGE_SZ, Ah, Bh,
                       m0, n0, Kp, kbase + (c + 3) * 32, tid);
        uint32_t sb = tile0 + (c & 3) * STAGE_SZ;
        #pragma unroll
        for (int kh = 0; kh < 2; kh++) {
            uint32_t ah[2][4], bh[4][4];
            #pragma unroll
            for (int ti = 0; ti < 2; ti++)
                ldsm4(ah[ti], sb + a_off[ti] + kh * 32);
            #pragma unroll
            for (int nt = 0; nt < 4; nt++)
                ldsm4(bh[nt], sb + B_HI_OFF + b_off[nt] + kh * 32);
            #pragma unroll
            for (int ti = 0; ti < 2; ti++)
                #pragma unroll
                for (int nt = 0; nt < 8; nt++)
                    mma_f16(acc[ti][nt], ah[ti], &bh[nt >> 1][(nt & 1) * 2]);
        }
    }

    float* Cout = (blockIdx.z == 0) ? C : C2;
    const int lr = lane >> 2, lc = (lane & 3) * 2;
    #pragma unroll
    for (int ti = 0; ti < 2; ti++)
        #pragma unroll
        for (int rp = 0; rp < 2; rp++) {
            int gr = m0 + mwoff + ti * 16 + rp * 8 + lr;
            if (gr >= N_NODES) continue;
            if (!SPLIT) {
                float* crow = Cout + (long)gr * ldC;
                #pragma unroll
                for (int nt = 0; nt < 8; nt++) {
                    int gc = n0 + nwoff + nt * 8 + lc;
                    float v0 = acc[ti][nt][rp * 2 + 0];
                    float v1 = acc[ti][nt][rp * 2 + 1];
                    if (gc < Nreal) {
                        if (BIAS) v0 += bias[gc];
                        if (ACT)  v0 = leaky(v0, 0.01f);
                        crow[gc] = v0;
                    }
                    if (gc + 1 < Nreal) {
                        if (BIAS) v1 += bias[gc + 1];
                        if (ACT)  v1 = leaky(v1, 0.01f);
                        crow[gc + 1] = v1;
                    }
                }
            } else {
                __half* hr = Sh + (long)gr * ldC;
                #pragma unroll
                for (int nt = 0; nt < 8; nt++) {
                    int gc = n0 + nwoff + nt * 8 + lc;
                    if (gc >= ldC) continue;
                    float v0 = 0.f, v1 = 0.f;
                    if (gc < Nreal) {
                        v0 = acc[ti][nt][rp * 2 + 0];
                        if (BIAS) v0 += bias[gc];
                        if (ACT)  v0 = leaky(v0, 0.01f);
                    }
                    if (gc + 1 < Nreal) {
                        v1 = acc[ti][nt][rp * 2 + 1];
                        if (BIAS) v1 += bias[gc + 1];
                        if (ACT)  v1 = leaky(v1, 0.01f);
                    }
                    __half2 hp;
                    hp.x = __float2half_rn(v0);
                    hp.y = __float2half_rn(v1);
                    *(__half2*)(hr + gc) = hp;
                }
            }
        }
}

// ---------------- GAT gather: single pass, full node range ----------------------
__global__ void gat_gather_kernel(const float* __restrict__ b_gat) {
    int gw = (blockIdx.x * blockDim.x + threadIdx.x) >> 5;
    int lane = threadIdx.x & 31;
    int wl = threadIdx.x >> 5;
    __shared__ float sal[8][12];
    if (gw >= N_NODES) return;
    int beg = g_rowptr[gw], end = g_rowptr[gw + 1];

    float adl = (lane < HEADS) ? g_ad[gw * HEADS + lane] : 0.f;

    int h0[3], pos[3], valid[3];
    #pragma unroll
    for (int j = 0; j < 3; j++) {
        int f4 = lane + 32 * j;
        valid[j] = (f4 < XTS / 8);
        int f0 = f4 * 8;
        int hh = f0 / FHEAD; if (hh > 9) hh = 9;
        h0[j] = hh;
        pos[j] = (hh + 1) * FHEAD - f0;
    }

    float acc[3][8] = {};
    float ssum = 0.f;

    for (int i = beg; i < end; i++) {
        int src = g_csr_src[i];
        if (lane < 12) {
            float w = (lane < HEADS)
                ? expf(leaky(g_as[src * HEADS + lane] + adl, 0.2f)) : 0.f;
            sal[wl][lane] = w;
            ssum += w;
        }
        __syncwarp();
        const float4* xs = (const float4*)(g_xth + (long)src * XTS);
        #pragma unroll
        for (int j = 0; j < 3; j++) {
            if (!valid[j]) continue;
            float4 raw = xs[lane + 32 * j];
            const __half2* hp = (const __half2*)&raw;
            float s0 = sal[wl][h0[j]], s1 = sal[wl][h0[j] + 1];
            #pragma unroll
            for (int k = 0; k < 4; k++) {
                float2 v = __half22float2(hp[k]);
                acc[j][2 * k + 0] += v.x * (2 * k     < pos[j] ? s0 : s1);
                acc[j][2 * k + 1] += v.y * (2 * k + 1 < pos[j] ? s0 : s1);
            }
        }
        __syncwarp();
    }

    if (lane < 12)
        sal[wl][lane] = (lane < HEADS) ? 1.f / fmaxf(ssum, 1e-16f) : 0.f;
    __syncwarp();

    __half* hd = g_h1h + (long)gw * XTS;
    #pragma unroll
    for (int j = 0; j < 3; j++) {
        if (!valid[j]) continue;
        int f0 = (lane + 32 * j) * 8;
        float i0 = sal[wl][h0[j]], i1 = sal[wl][h0[j] + 1];
        __half2 o[4];
        #pragma unroll
        for (int k = 0; k < 8; k++) {
            int f = f0 + k;
            float inv = (k < pos[j]) ? i0 : i1;
            float v = (f < D1) ? leaky(acc[j][k] * inv + b_gat[f], 0.01f) : 0.f;
            ((__half*)o)[k] = __float2half_rn(v);
        }
        *(float4*)(hd + f0) = *(float4*)o;
    }
}

// ---------------- GCN gather over node range [node0, node0+ncount) ---------------
__global__ void gcn_gather_kernel(int node0, int ncount) {
    int gw = node0 + ((blockIdx.x * blockDim.x + threadIdx.x) >> 5);
    int lane = threadIdx.x & 31;
    if (gw >= node0 + ncount || gw >= N_NODES) return;
    int beg = g_rowptr[gw], end = g_rowptr[gw + 1];
    float dd = g_dinv[gw];

    float acc[3][8] = {};
    int valid[3];
    #pragma unroll
    for (int j = 0; j < 3; j++) valid[j] = (lane + 32 * j) < XTS / 8;

    for (int i = beg; i < end; i++) {
        int src = g_csr_src[i];
        float nm = dd * g_dinv[src];
        const float4* hs = (const float4*)(g_h1h + (long)src * XTS);
        #pragma unroll
        for (int j = 0; j < 3; j++) {
            if (!valid[j]) continue;
            float4 raw = hs[lane + 32 * j];
            const __half2* hp = (const __half2*)&raw;
            #pragma unroll
            for (int k = 0; k < 4; k++) {
                float2 v = __half22float2(hp[k]);
                acc[j][2 * k + 0] += v.x * nm;
                acc[j][2 * k + 1] += v.y * nm;
            }
        }
    }

    __half* hr = g_aah + (long)gw * KP_AGG;
    #pragma unroll
    for (int j = 0; j < 3; j++) {
        if (!valid[j]) continue;
        int f0 = (lane + 32 * j) * 8;
        __half2 o[4];
        #pragma unroll
        for (int k = 0; k < 8; k++)
            ((__half*)o)[k] = __float2half_rn(acc[j][k]);
        *(float4*)(hr + f0) = *(float4*)o;
    }
}

// ---------------- tail over node range --------------------------------------------
__global__ void tail_kernel(const float* __restrict__ W1, const float* __restrict__ b1,
                            const float* __restrict__ W2, const float* __restrict__ b2,
                            const float* __restrict__ W3, const float* __restrict__ b3,
                            const float* __restrict__ bg2,
                            float* __restrict__ out, int node0, int ncount) {
    int gw = node0 + ((blockIdx.x * blockDim.x + threadIdx.x) >> 5);
    int lane = threadIdx.x & 31;
    if (gw >= node0 + ncount || gw >= N_NODES) return;
    float v0 = leaky(g_h4a[gw * 64 + lane] + g_h4b[gw * 64 + lane] + bg2[lane], 0.01f);
    float v1 = leaky(g_h4a[gw * 64 + 32 + lane] + g_h4b[gw * 64 + 32 + lane] + bg2[32 + lane], 0.01f);
    float s = b1[lane];
    #pragma unroll
    for (int k = 0; k < 32; k++) s += __shfl_sync(0xffffffffu, v0, k) * W1[k * 32 + lane];
    #pragma unroll
    for (int k = 0; k < 32; k++) s += __shfl_sync(0xffffffffu, v1, k) * W1[(k + 32) * 32 + lane];
    float u = leaky(s, 0.01f);
    int j = lane & 15;
    float s2 = b2[j];
    #pragma unroll
    for (int k = 0; k < 32; k++) s2 += __shfl_sync(0xffffffffu, u, k) * W2[k * 16 + j];
    float t = leaky(s2, 0.01f);
    float o = (lane < 16) ? t * W3[lane] : 0.f;
    #pragma unroll
    for (int off = 8; off > 0; off >>= 1) o += __shfl_down_sync(0xffffffffu, o, off);
    if (lane == 0) out[gw] = o + b3[0];
}

// ---------------- launch --------------------------------------------------------------
extern "C" void kernel_launch(void* const* d_in, const int* in_sizes, int n_in,
                              void* d_out, int out_size) {
    const float* x     = (const float*)d_in[0];
    const int*   ei    = (const int*)  d_in[1];
    const float* W_gat = (const float*)d_in[2];
    const float* att_s = (const float*)d_in[3];
    const float* att_d = (const float*)d_in[4];
    const float* b_gat = (const float*)d_in[5];
    const float* W_gcn = (const float*)d_in[6];
    const float* b_gcn = (const float*)d_in[7];
    const float* W_g1  = (const float*)d_in[8];
    const float* b_g1  = (const float*)d_in[9];
    const float* W_g2  = (const float*)d_in[10];
    const float* b_g2  = (const float*)d_in[11];
    const float* W_fc1 = (const float*)d_in[12];
    const float* b_fc1 = (const float*)d_in[13];
    const float* W_fc2 = (const float*)d_in[14];
    const float* b_fc2 = (const float*)d_in[15];
    const float* W_out = (const float*)d_in[16];
    const float* b_out = (const float*)d_in[17];
    float* out = (float*)d_out;
    (void)in_sizes; (void)n_in; (void)out_size;

    cudaFuncSetAttribute(mma_gemm<false, false, true>, cudaFuncAttributeMaxDynamicSharedMemorySize, GEMM_SMEM);
    cudaFuncSetAttribute(mma_gemm<true, true, true>,   cudaFuncAttributeMaxDynamicSharedMemorySize, GEMM_SMEM);
    cudaFuncSetAttribute(mma_gemm<false, false, false>, cudaFuncAttributeMaxDynamicSharedMemorySize, GEMM_SMEM);

    float *p_h4a, *p_h4b;
    cudaGetSymbolAddress((void**)&p_h4a, g_h4a);
    cudaGetSymbolAddress((void**)&p_h4b, g_h4b);
    #define HADDR(p, s) __half* p; cudaGetSymbolAddress((void**)&p, s)
    HADDR(axh, g_axh); HADDR(aah, g_aah);
    HADDR(a2h, g_a2h); HADDR(a3h, g_a3h);
    HADDR(bgat, g_bgat); HADDR(bgcn, g_bgcn);
    HADDR(bg1, g_bg1); HADDR(bg2, g_bg2);
    HADDR(xth, g_xth);

    cudaStream_t s2, s3;
    cudaStreamCreateWithFlags(&s2, cudaStreamNonBlocking);
    cudaStreamCreateWithFlags(&s3, cudaStreamNonBlocking);
    cudaEvent_t e_fork, e_csr, e_asd, e_cvt, e_h1, e_done2;
    cudaEventCreateWithFlags(&e_fork, cudaEventDisableTiming);
    cudaEventCreateWithFlags(&e_csr,  cudaEventDisableTiming);
    cudaEventCreateWithFlags(&e_asd,  cudaEventDisableTiming);
    cudaEventCreateWithFlags(&e_cvt,  cudaEventDisableTiming);
    cudaEventCreateWithFlags(&e_h1,   cudaEventDisableTiming);
    cudaEventCreateWithFlags(&e_done2, cudaEventDisableTiming);

    cudaEventRecord(e_fork, 0);
    cudaStreamWaitEvent(s2, e_fork, 0);
    cudaStreamWaitEvent(s3, e_fork, 0);

    // s2: CSR chain, then non-critical converts
    zero_small_kernel<<<(N_NODES + 255) / 256, 256, 0, s2>>>();
    deg_kernel<<<(E_TOT + 255) / 256, 256, 0, s2>>>(ei);
    scan_kernel<<<1, 1024, 0, s2>>>();
    fill_kernel<<<(E_TOT + 255) / 256, 256, 0, s2>>>(ei);
    cudaEventRecord(e_csr, s2);
    cvt_rest_kernel<<<(CVT_REST + 255) / 256, 256, 0, s2>>>(W_gcn, W_g1, W_g2);
    cudaEventRecord(e_cvt, s2);

    // s3: attention coefficients
    ws_kernel<<<(HEADS * F_IN + 255) / 256, 256, 0, s3>>>(W_gat, att_s, att_d);
    asd_kernel<<<(N_NODES * HEADS + 255) / 256, 256, 0, s3>>>(x);
    cudaEventRecord(e_asd, s3);

    // main: critical converts -> GAT GEMM
    cvt_crit_kernel<<<(CVT_CRIT + 255) / 256, 256>>>(x, W_gat);
    mma_gemm<false, false, true><<<dim3(NP_GAT / 128, M_PAD / 128), 256, GEMM_SMEM>>>(
        axh, bgat, nullptr, nullptr, nullptr, xth, KP_X, KP_X / 32, D1, XTS, 0);

    cudaStreamWaitEvent(0, e_csr, 0);
    cudaStreamWaitEvent(0, e_asd, 0);

    gat_gather_kernel<<<(N_NODES * 32 + 255) / 256, 256>>>(b_gat);
    cudaEventRecord(e_h1, 0);

    // fork the row-local post-h1 stack into two M-halves:
    // half 0 stays on default stream; half 1 on s2.
    cudaStreamWaitEvent(s2, e_h1, 0);
    // (e_cvt was recorded on s2, so s2's half-1 chain already orders after it;
    //  default stream must wait for it before its GEMMs)

    const int N0 = MSPLIT_NODE, N1 = N_NODES - MSPLIT_NODE;

    // half 0 (default stream)
    gcn_gather_kernel<<<(N0 * 32 + 255) / 256, 256>>>(0, N0);
    cudaStreamWaitEvent(0, e_cvt, 0);
    mma_gemm<true, true, true><<<dim3(NP_GCN / 128, MBLK0), 256, GEMM_SMEM>>>(
        aah, bgcn, b_gcn, nullptr, nullptr, a2h, KP_AGG, KP_AGG / 32, D2, KP_H2, 0);
    mma_gemm<true, true, true><<<dim3(NP_G1 / 128, MBLK0), 256, GEMM_SMEM>>>(
        a2h, bg1, b_g1, nullptr, nullptr, a3h, KP_H2, KP_H2 / 32, D3, KP_H3, 0);
    mma_gemm<false, false, false><<<dim3(NP_G2 / 128, MBLK0, 2), 256, GEMM_SMEM>>>(
        a3h, bg2, nullptr, p_h4a, p_h4b, nullptr, KP_H3, KP_H3 / 64, D4, D4, 0);
    tail_kernel<<<(N0 * 32 + 255) / 256, 256>>>(
        W_fc1, b_fc1, W_fc2, b_fc2, W_out, b_out, b_g2, out, 0, N0);

    // half 1 (stream s2)
    gcn_gather_kernel<<<(N1 * 32 + 255) / 256, 256, 0, s2>>>(MSPLIT_NODE, N1);
    mma_gemm<true, true, true><<<dim3(NP_GCN / 128, MBLK1), 256, GEMM_SMEM, s2>>>(
        aah, bgcn, b_gcn, nullptr, nullptr, a2h, KP_AGG, KP_AGG / 32, D2, KP_H2, MBLK0);
    mma_gemm<true, true, true><<<dim3(NP_G1 / 128, MBLK1), 256, GEMM_SMEM, s2>>>(
        a2h, bg1, b_g1, nullptr, nullptr, a3h, KP_H2, KP_H2 / 32, D3, KP_H3, MBLK0);
    mma_gemm<false, false, false><<<dim3(NP_G2 / 128, MBLK1, 2), 256, GEMM_SMEM, s2>>>(
        a3h, bg2, nullptr, p_h4a, p_h4b, nullptr, KP_H3, KP_H3 / 64, D4, D4, MBLK0);
    tail_kernel<<<(N1 * 32 + 255) / 256, 256, 0, s2>>>(
        W_fc1, b_fc1, W_fc2, b_fc2, W_out, b_out, b_g2, out, MSPLIT_NODE, N1);
    cudaEventRecord(e_done2, s2);

    // join half 1 into default stream
    cudaStreamWaitEvent(0, e_done2, 0);

    cudaEventDestroy(e_fork);
    cudaEventDestroy(e_csr);
    cudaEventDestroy(e_asd);
    cudaEventDestroy(e_cvt);
    cudaEventDestroy(e_h1);
    cudaEventDestroy(e_done2);
    cudaStreamDestroy(s2);
    cudaStreamDestroy(s3);
}

// round 13
// speedup vs baseline: 1.4673x; 1.0334x over previous
#include <cuda_runtime.h>
#include <cuda_fp16.h>
#include <math.h>
#include <stdint.h>

#define N_NODES 10000
#define N_EDGES 120000
#define E_TOT   130000
#define F_IN    66
#define HEADS   10
#define FHEAD   66
#define D1      660
#define D2      1320
#define D3      1000
#define D4      64
#define M_PAD   10112        // 79 * 128

#define KP_X    128          // mult of 64
#define KP_AGG  704          // mult of 64; cols [672,704) stay zero (static init)
#define KP_H2   1344
#define KP_H3   1024
#define NP_GAT  768
#define NP_GCN  1408
#define NP_G1   1024
#define NP_G2   128
#define XTS     672

#define MSPLIT_NODE 5120
#define MBLK0 40
#define MBLK1 39

// ---------------- scratch ------------------------------------------------------
__device__             float g_as [N_NODES * HEADS];
__device__             float g_ad [N_NODES * HEADS];
__device__             float g_ws [HEADS * F_IN];
__device__             float g_wd [HEADS * F_IN];
__device__             float g_dinv[N_NODES];
__device__ __align__(16) float g_h4a[N_NODES * D4];
__device__ __align__(16) float g_h4b[N_NODES * D4];

__device__ __align__(16) __half g_xth [N_NODES * XTS];
__device__ __align__(16) __half g_h1h [N_NODES * XTS];

// ---------------- CSR over destination ------------------------------------------
__device__ int g_deg_i [N_NODES];
__device__ int g_fill  [N_NODES];
__device__ int g_rowptr[N_NODES + 1];
__device__ int g_csr_src[E_TOT];

// ---------------- fp16 GEMM buffers ----------------------------------------------
__device__ __align__(16) __half g_axh [M_PAD * KP_X];
__device__ __align__(16) __half g_aah [M_PAD * KP_AGG];   // pad cols stay 0
__device__ __align__(16) __half g_a2h [M_PAD * KP_H2];
__device__ __align__(16) __half g_a3h [M_PAD * KP_H3];
__device__ __align__(16) __half g_bgat[NP_GAT * KP_X];
__device__ __align__(16) __half g_bgcn[NP_GCN * KP_AGG];
__device__ __align__(16) __half g_bg1 [NP_G1 * KP_H2];
__device__ __align__(16) __half g_bg2 [NP_G2 * KP_H3];

// ---------------- baseline-PTX helpers -------------------------------------------
__device__ __forceinline__ uint32_t smem_u32(const void* p) {
    uint32_t a;
    asm("{ .reg .u64 t; cvta.to.shared.u64 t, %1; cvt.u32.u64 %0, t; }" : "=r"(a) : "l"(p));
    return a;
}
__device__ __forceinline__ void cp16(uint32_t dst, const void* src) {
    asm volatile("cp.async.cg.shared.global [%0], [%1], 16;" :: "r"(dst), "l"(src));
}
__device__ __forceinline__ void cp_commit() { asm volatile("cp.async.commit_group;"); }
template<int N> __device__ __forceinline__ void cp_wait() {
    asm volatile("cp.async.wait_group %0;" :: "n"(N));
}
__device__ __forceinline__ void ldsm4(uint32_t* r, uint32_t addr) {
    asm volatile("ldmatrix.sync.aligned.m8n8.x4.shared.b16 {%0,%1,%2,%3}, [%4];"
        : "=r"(r[0]), "=r"(r[1]), "=r"(r[2]), "=r"(r[3]) : "r"(addr));
}
__device__ __forceinline__ void mma_f16(float* d, const uint32_t* a, const uint32_t* b) {
    asm volatile("mma.sync.aligned.m16n8k16.row.col.f32.f16.f16.f32 "
        "{%0,%1,%2,%3}, {%4,%5,%6,%7}, {%8,%9}, {%0,%1,%2,%3};"
        : "+f"(d[0]), "+f"(d[1]), "+f"(d[2]), "+f"(d[3])
        : "r"(a[0]), "r"(a[1]), "r"(a[2]), "r"(a[3]), "r"(b[0]), "r"(b[1]));
}

// ---------------- misc ------------------------------------------------------------
__device__ __forceinline__ void edge_sd(const int* ei, int e, int& s, int& d) {
    if (e < N_EDGES) { s = ei[e]; d = ei[N_EDGES + e]; }
    else             { s = d = e - N_EDGES; }
}
__device__ __forceinline__ float leaky(float v, float sl) { return v >= 0.f ? v : sl * v; }

// ---------------- CSR build ---------------------------------------------------------
__global__ void zero_small_kernel() {
    int i = blockIdx.x * blockDim.x + threadIdx.x;
    if (i < N_NODES) { g_deg_i[i] = 0; g_fill[i] = 0; }
}
__global__ void deg_kernel(const int* __restrict__ ei) {
    int e = blockIdx.x * blockDim.x + threadIdx.x;
    if (e >= E_TOT) return;
    int s, d; edge_sd(ei, e, s, d);
    atomicAdd(&g_deg_i[d], 1);
}
__global__ void scan_kernel() {
    __shared__ int sm[1024];
    int tid = threadIdx.x;
    int base = tid * 10;
    int local[10]; int sum = 0;
    #pragma unroll
    for (int i = 0; i < 10; i++) {
        int v = (base + i < N_NODES) ? g_deg_i[base + i] : 0;
        if (base + i < N_NODES) g_dinv[base + i] = rsqrtf(fmaxf((float)v, 1.f));
        local[i] = sum; sum += v;
    }
    sm[tid] = sum; __syncthreads();
    for (int off = 1; off < 1024; off <<= 1) {
        int v = (tid >= off) ? sm[tid - off] : 0;
        __syncthreads();
        sm[tid] += v;
        __syncthreads();
    }
    int pre = (tid > 0) ? sm[tid - 1] : 0;
    #pragma unroll
    for (int i = 0; i < 10; i++)
        if (base + i < N_NODES) g_rowptr[base + i] = pre + local[i];
    if (tid == 1023) g_rowptr[N_NODES] = sm[1023];
}
__global__ void fill_kernel(const int* __restrict__ ei) {
    int e = blockIdx.x * blockDim.x + threadIdx.x;
    if (e >= E_TOT) return;
    int s, d; edge_sd(ei, e, s, d);
    int pos = atomicAdd(&g_fill[d], 1);
    g_csr_src[g_rowptr[d] + pos] = s;
}

// ---------------- attn hoist --------------------------------------------------------
__global__ void ws_kernel(const float* __restrict__ Wgat,
                          const float* __restrict__ att_s, const float* __restrict__ att_d) {
    int idx = blockIdx.x * blockDim.x + threadIdx.x;
    if (idx >= HEADS * F_IN) return;
    int h = idx / F_IN, i = idx - h * F_IN;
    const float* wrow = Wgat + (long)i * D1 + h * FHEAD;
    const float* as = att_s + h * FHEAD;
    const float* ad = att_d + h * FHEAD;
    float s = 0.f, d = 0.f;
    #pragma unroll
    for (int f = 0; f < FHEAD; f++) { float w = wrow[f]; s += w * as[f]; d += w * ad[f]; }
    g_ws[idx] = s; g_wd[idx] = d;
}
__global__ void asd_kernel(const float* __restrict__ x) {
    int idx = blockIdx.x * blockDim.x + threadIdx.x;
    if (idx >= N_NODES * HEADS) return;
    int n = idx / HEADS, h = idx - n * HEADS;
    const float* xr = x + (long)n * F_IN;
    const float* ws = g_ws + h * F_IN;
    const float* wd = g_wd + h * F_IN;
    float s = 0.f, d = 0.f;
    #pragma unroll
    for (int i = 0; i < F_IN; i++) { float v = xr[i]; s += v * ws[i]; d += v * wd[i]; }
    g_as[idx] = s; g_ad[idx] = d;
}

// ---------------- converts ------------------------------------------------------------
#define R0 (NP_GAT * KP_X)
#define R4 (M_PAD * KP_X)
#define CVT_CRIT (R0 + R4)
#define R1 (NP_GCN * KP_AGG)
#define R2 (NP_G1 * KP_H2)
#define R3 (NP_G2 * KP_H3)
#define CVT_REST (R1 + R2 + R3)

__device__ __forceinline__ void cvtB_one(const float* W, __half* dst, int idx,
                                         int K, int Nn, int Kp) {
    int n = idx / Kp, k = idx - n * Kp;
    float v = (k < K && n < Nn) ? W[(long)k * Nn + n] : 0.f;
    dst[idx] = __float2half_rn(v);
}
__global__ void cvt_crit_kernel(const float* __restrict__ x, const float* __restrict__ Wgat) {
    int idx = blockIdx.x * blockDim.x + threadIdx.x;
    if (idx >= CVT_CRIT) return;
    if (idx < R0) { cvtB_one(Wgat, g_bgat, idx, F_IN, D1, KP_X); return; }
    idx -= R0;
    int r = idx / KP_X, c = idx - r * KP_X;
    float v = (r < N_NODES && c < F_IN) ? x[(long)r * F_IN + c] : 0.f;
    g_axh[idx] = __float2half_rn(v);
}
__global__ void cvt_rest_kernel(const float* __restrict__ Wgcn,
                                const float* __restrict__ Wg1, const float* __restrict__ Wg2) {
    int idx = blockIdx.x * blockDim.x + threadIdx.x;
    if (idx >= CVT_REST) return;
    if (idx < R1) { cvtB_one(Wgcn, g_bgcn, idx, D1, D2, KP_AGG); return; }
    idx -= R1;
    if (idx < R2) { cvtB_one(Wg1, g_bg1, idx, D2, D3, KP_H2); return; }
    idx -= R2;
    cvtB_one(Wg2, g_bg2, idx, D3, D4, KP_H3);
}

// ---------------- HMMA GEMM: BK=64, 3-stage cp.async, 2 CTAs/SM -----------------------
#define TSTRIDE  144         // 128B data + 16B pad; 16B-units 9r mod 32 conflict-free
#define B_HI_OFF 18432       // 128 * 144
#define STAGE_SZ 36864
#define GEMM_SMEM (3 * STAGE_SZ)

__device__ __forceinline__ void fill_stage(uint32_t st,
        const __half* __restrict__ A, const __half* __restrict__ B,
        int m0, int n0, int Kp, int k0, int tid) {
    #pragma unroll
    for (int i = 0; i < 4; i++) {
        int lin = tid + i * 256;          // 0..1023
        int r = lin >> 3, cc = lin & 7;
        uint32_t d = st + r * TSTRIDE + cc * 16;
        cp16(d,            (const char*)(A + (long)(m0 + r) * Kp + k0) + cc * 16);
        cp16(d + B_HI_OFF, (const char*)(B + (long)(n0 + r) * Kp + k0) + cc * 16);
    }
    cp_commit();
}

template<bool BIAS, bool ACT, bool SPLIT>
__global__ __launch_bounds__(256, 2)
void mma_gemm(const __half* __restrict__ Ah, const __half* __restrict__ Bh,
              const float* __restrict__ bias, float* __restrict__ C,
              float* __restrict__ C2, __half* __restrict__ Sh,
              int Kp, int chunks, int Nreal, int ldC, int mblk_off) {
    extern __shared__ char smem[];
    const uint32_t tile0 = smem_u32(smem);
    const int tid = threadIdx.x, wid = tid >> 5, lane = tid & 31;
    const int m0 = (blockIdx.y + mblk_off) * 128, n0 = blockIdx.x * 128;
    const int kbase = blockIdx.z * chunks * 64;
    const int mwoff = (wid >> 1) * 32, nwoff = (wid & 1) * 64;

    const int mat = lane >> 3, mrow = lane & 7;
    uint32_t a_off[2], b_off[4];
    #pragma unroll
    for (int ti = 0; ti < 2; ti++)
        a_off[ti] = (uint32_t)((mwoff + ti * 16 + ((mat & 1) << 3) + mrow) * TSTRIDE
                               + (mat >> 1) * 16);
    #pragma unroll
    for (int nt = 0; nt < 4; nt++)
        b_off[nt] = (uint32_t)((nwoff + nt * 16 + ((mat >> 1) << 3) + mrow) * TSTRIDE
                               + (mat & 1) * 16);

    float acc[2][8][4] = {};

    fill_stage(tile0, Ah, Bh, m0, n0, Kp, kbase, tid);
    if (chunks > 1) fill_stage(tile0 + STAGE_SZ, Ah, Bh, m0, n0, Kp, kbase + 64, tid);

    int sidx = 0;
    for (int c = 0; c < chunks; c++) {
        if (c + 1 < chunks) cp_wait<1>(); else cp_wait<0>();
        __syncthreads();
        if (c + 2 < chunks) {
            int nxt = sidx + 2; if (nxt >= 3) nxt -= 3;
            fill_stage(tile0 + nxt * STAGE_SZ, Ah, Bh, m0, n0, Kp, kbase + (c + 2) * 64, tid);
        }
        uint32_t sb = tile0 + sidx * STAGE_SZ;
        #pragma unroll
        for (int kh = 0; kh < 4; kh++) {
            uint32_t ah[2][4], bh[4][4];
            #pragma unroll
            for (int ti = 0; ti < 2; ti++)
                ldsm4(ah[ti], sb + a_off[ti] + kh * 32);
            #pragma unroll
            for (int nt = 0; nt < 4; nt++)
                ldsm4(bh[nt], sb + B_HI_OFF + b_off[nt] + kh * 32);
            #pragma unroll
            for (int ti = 0; ti < 2; ti++)
                #pragma unroll
                for (int nt = 0; nt < 8; nt++)
                    mma_f16(acc[ti][nt], ah[ti], &bh[nt >> 1][(nt & 1) * 2]);
        }
        if (++sidx >= 3) sidx = 0;
    }

    float* Cout = (blockIdx.z == 0) ? C : C2;
    const int lr = lane >> 2, lc = (lane & 3) * 2;
    #pragma unroll
    for (int ti = 0; ti < 2; ti++)
        #pragma unroll
        for (int rp = 0; rp < 2; rp++) {
            int gr = m0 + mwoff + ti * 16 + rp * 8 + lr;
            if (gr >= N_NODES) continue;
            if (!SPLIT) {
                float* crow = Cout + (long)gr * ldC;
                #pragma unroll
                for (int nt = 0; nt < 8; nt++) {
                    int gc = n0 + nwoff + nt * 8 + lc;
                    float v0 = acc[ti][nt][rp * 2 + 0];
                    float v1 = acc[ti][nt][rp * 2 + 1];
                    if (gc < Nreal) {
                        if (BIAS) v0 += bias[gc];
                        if (ACT)  v0 = leaky(v0, 0.01f);
                        crow[gc] = v0;
                    }
                    if (gc + 1 < Nreal) {
                        if (BIAS) v1 += bias[gc + 1];
                        if (ACT)  v1 = leaky(v1, 0.01f);
                        crow[gc + 1] = v1;
                    }
                }
            } else {
                __half* hr = Sh + (long)gr * ldC;
                #pragma unroll
                for (int nt = 0; nt < 8; nt++) {
                    int gc = n0 + nwoff + nt * 8 + lc;
                    if (gc >= ldC) continue;
                    float v0 = 0.f, v1 = 0.f;
                    if (gc < Nreal) {
                        v0 = acc[ti][nt][rp * 2 + 0];
                        if (BIAS) v0 += bias[gc];
                        if (ACT)  v0 = leaky(v0, 0.01f);
                    }
                    if (gc + 1 < Nreal) {
                        v1 = acc[ti][nt][rp * 2 + 1];
                        if (BIAS) v1 += bias[gc + 1];
                        if (ACT)  v1 = leaky(v1, 0.01f);
                    }
                    __half2 hp;
                    hp.x = __float2half_rn(v0);
                    hp.y = __float2half_rn(v1);
                    *(__half2*)(hr + gc) = hp;
                }
            }
        }
}

// ---------------- GAT gather: single pass ----------------------------------------
__global__ void gat_gather_kernel(const float* __restrict__ b_gat) {
    int gw = (blockIdx.x * blockDim.x + threadIdx.x) >> 5;
    int lane = threadIdx.x & 31;
    int wl = threadIdx.x >> 5;
    __shared__ float sal[8][12];
    if (gw >= N_NODES) return;
    int beg = g_rowptr[gw], end = g_rowptr[gw + 1];

    float adl = (lane < HEADS) ? g_ad[gw * HEADS + lane] : 0.f;

    int h0[3], pos[3], valid[3];
    #pragma unroll
    for (int j = 0; j < 3; j++) {
        int f4 = lane + 32 * j;
        valid[j] = (f4 < XTS / 8);
        int f0 = f4 * 8;
        int hh = f0 / FHEAD; if (hh > 9) hh = 9;
        h0[j] = hh;
        pos[j] = (hh + 1) * FHEAD - f0;
    }

    float acc[3][8] = {};
    float ssum = 0.f;

    for (int i = beg; i < end; i++) {
        int src = g_csr_src[i];
        if (lane < 12) {
            float w = (lane < HEADS)
                ? expf(leaky(g_as[src * HEADS + lane] + adl, 0.2f)) : 0.f;
            sal[wl][lane] = w;
            ssum += w;
        }
        __syncwarp();
        const float4* xs = (const float4*)(g_xth + (long)src * XTS);
        #pragma unroll
        for (int j = 0; j < 3; j++) {
            if (!valid[j]) continue;
            float4 raw = xs[lane + 32 * j];
            const __half2* hp = (const __half2*)&raw;
            float s0 = sal[wl][h0[j]], s1 = sal[wl][h0[j] + 1];
            #pragma unroll
            for (int k = 0; k < 4; k++) {
                float2 v = __half22float2(hp[k]);
                acc[j][2 * k + 0] += v.x * (2 * k     < pos[j] ? s0 : s1);
                acc[j][2 * k + 1] += v.y * (2 * k + 1 < pos[j] ? s0 : s1);
            }
        }
        __syncwarp();
    }

    if (lane < 12)
        sal[wl][lane] = (lane < HEADS) ? 1.f / fmaxf(ssum, 1e-16f) : 0.f;
    __syncwarp();

    __half* hd = g_h1h + (long)gw * XTS;
    #pragma unroll
    for (int j = 0; j < 3; j++) {
        if (!valid[j]) continue;
        int f0 = (lane + 32 * j) * 8;
        float i0 = sal[wl][h0[j]], i1 = sal[wl][h0[j] + 1];
        __half2 o[4];
        #pragma unroll
        for (int k = 0; k < 8; k++) {
            int f = f0 + k;
            float inv = (k < pos[j]) ? i0 : i1;
            float v = (f < D1) ? leaky(acc[j][k] * inv + b_gat[f], 0.01f) : 0.f;
            ((__half*)o)[k] = __float2half_rn(v);
        }
        *(float4*)(hd + f0) = *(float4*)o;
    }
}

// ---------------- GCN gather over node range ---------------------------------------
__global__ void gcn_gather_kernel(int node0, int ncount) {
    int gw = node0 + ((blockIdx.x * blockDim.x + threadIdx.x) >> 5);
    int lane = threadIdx.x & 31;
    if (gw >= node0 + ncount || gw >= N_NODES) return;
    int beg = g_rowptr[gw], end = g_rowptr[gw + 1];
    float dd = g_dinv[gw];

    float acc[3][8] = {};
    int valid[3];
    #pragma unroll
    for (int j = 0; j < 3; j++) valid[j] = (lane + 32 * j) < XTS / 8;

    for (int i = beg; i < end; i++) {
        int src = g_csr_src[i];
        float nm = dd * g_dinv[src];
        const float4* hs = (const float4*)(g_h1h + (long)src * XTS);
        #pragma unroll
        for (int j = 0; j < 3; j++) {
            if (!valid[j]) continue;
            float4 raw = hs[lane + 32 * j];
            const __half2* hp = (const __half2*)&raw;
            #pragma unroll
            for (int k = 0; k < 4; k++) {
                float2 v = __half22float2(hp[k]);
                acc[j][2 * k + 0] += v.x * nm;
                acc[j][2 * k + 1] += v.y * nm;
            }
        }
    }

    __half* hr = g_aah + (long)gw * KP_AGG;   // cols [XTS, KP_AGG) remain 0 (static init)
    #pragma unroll
    for (int j = 0; j < 3; j++) {
        if (!valid[j]) continue;
        int f0 = (lane + 32 * j) * 8;
        __half2 o[4];
        #pragma unroll
        for (int k = 0; k < 8; k++)
            ((__half*)o)[k] = __float2half_rn(acc[j][k]);
        *(float4*)(hr + f0) = *(float4*)o;
    }
}

// ---------------- tail over node range ----------------------------------------------
__global__ void tail_kernel(const float* __restrict__ W1, const float* __restrict__ b1,
                            const float* __restrict__ W2, const float* __restrict__ b2,
                            const float* __restrict__ W3, const float* __restrict__ b3,
                            const float* __restrict__ bg2,
                            float* __restrict__ out, int node0, int ncount) {
    int gw = node0 + ((blockIdx.x * blockDim.x + threadIdx.x) >> 5);
    int lane = threadIdx.x & 31;
    if (gw >= node0 + ncount || gw >= N_NODES) return;
    float v0 = leaky(g_h4a[gw * 64 + lane] + g_h4b[gw * 64 + lane] + bg2[lane], 0.01f);
    float v1 = leaky(g_h4a[gw * 64 + 32 + lane] + g_h4b[gw * 64 + 32 + lane] + bg2[32 + lane], 0.01f);
    float s = b1[lane];
    #pragma unroll
    for (int k = 0; k < 32; k++) s += __shfl_sync(0xffffffffu, v0, k) * W1[k * 32 + lane];
    #pragma unroll
    for (int k = 0; k < 32; k++) s += __shfl_sync(0xffffffffu, v1, k) * W1[(k + 32) * 32 + lane];
    float u = leaky(s, 0.01f);
    int j = lane & 15;
    float s2 = b2[j];
    #pragma unroll
    for (int k = 0; k < 32; k++) s2 += __shfl_sync(0xffffffffu, u, k) * W2[k * 16 + j];
    float t = leaky(s2, 0.01f);
    float o = (lane < 16) ? t * W3[lane] : 0.f;
    #pragma unroll
    for (int off = 8; off > 0; off >>= 1) o += __shfl_down_sync(0xffffffffu, o, off);
    if (lane == 0) out[gw] = o + b3[0];
}

// ---------------- launch --------------------------------------------------------------
extern "C" void kernel_launch(void* const* d_in, const int* in_sizes, int n_in,
                              void* d_out, int out_size) {
    const float* x     = (const float*)d_in[0];
    const int*   ei    = (const int*)  d_in[1];
    const float* W_gat = (const float*)d_in[2];
    const float* att_s = (const float*)d_in[3];
    const float* att_d = (const float*)d_in[4];
    const float* b_gat = (const float*)d_in[5];
    const float* W_gcn = (const float*)d_in[6];
    const float* b_gcn = (const float*)d_in[7];
    const float* W_g1  = (const float*)d_in[8];
    const float* b_g1  = (const float*)d_in[9];
    const float* W_g2  = (const float*)d_in[10];
    const float* b_g2  = (const float*)d_in[11];
    const float* W_fc1 = (const float*)d_in[12];
    const float* b_fc1 = (const float*)d_in[13];
    const float* W_fc2 = (const float*)d_in[14];
    const float* b_fc2 = (const float*)d_in[15];
    const float* W_out = (const float*)d_in[16];
    const float* b_out = (const float*)d_in[17];
    float* out = (float*)d_out;
    (void)in_sizes; (void)n_in; (void)out_size;

    cudaFuncSetAttribute(mma_gemm<false, false, true>, cudaFuncAttributeMaxDynamicSharedMemorySize, GEMM_SMEM);
    cudaFuncSetAttribute(mma_gemm<true, true, true>,   cudaFuncAttributeMaxDynamicSharedMemorySize, GEMM_SMEM);
    cudaFuncSetAttribute(mma_gemm<false, false, false>, cudaFuncAttributeMaxDynamicSharedMemorySize, GEMM_SMEM);

    float *p_h4a, *p_h4b;
    cudaGetSymbolAddress((void**)&p_h4a, g_h4a);
    cudaGetSymbolAddress((void**)&p_h4b, g_h4b);
    #define HADDR(p, s) __half* p; cudaGetSymbolAddress((void**)&p, s)
    HADDR(axh, g_axh); HADDR(aah, g_aah);
    HADDR(a2h, g_a2h); HADDR(a3h, g_a3h);
    HADDR(bgat, g_bgat); HADDR(bgcn, g_bgcn);
    HADDR(bg1, g_bg1); HADDR(bg2, g_bg2);
    HADDR(xth, g_xth);

    cudaStream_t s2, s3;
    cudaStreamCreateWithFlags(&s2, cudaStreamNonBlocking);
    cudaStreamCreateWithFlags(&s3, cudaStreamNonBlocking);
    cudaEvent_t e_fork, e_csr, e_asd, e_cvt, e_h1, e_done2;
    cudaEventCreateWithFlags(&e_fork, cudaEventDisableTiming);
    cudaEventCreateWithFlags(&e_csr,  cudaEventDisableTiming);
    cudaEventCreateWithFlags(&e_asd,  cudaEventDisableTiming);
    cudaEventCreateWithFlags(&e_cvt,  cudaEventDisableTiming);
    cudaEventCreateWithFlags(&e_h1,   cudaEventDisableTiming);
    cudaEventCreateWithFlags(&e_done2, cudaEventDisableTiming);

    cudaEventRecord(e_fork, 0);
    cudaStreamWaitEvent(s2, e_fork, 0);
    cudaStreamWaitEvent(s3, e_fork, 0);

    // s2: CSR chain, then non-critical converts
    zero_small_kernel<<<(N_NODES + 255) / 256, 256, 0, s2>>>();
    deg_kernel<<<(E_TOT + 255) / 256, 256, 0, s2>>>(ei);
    scan_kernel<<<1, 1024, 0, s2>>>();
    fill_kernel<<<(E_TOT + 255) / 256, 256, 0, s2>>>(ei);
    cudaEventRecord(e_csr, s2);
    cvt_rest_kernel<<<(CVT_REST + 255) / 256, 256, 0, s2>>>(W_gcn, W_g1, W_g2);
    cudaEventRecord(e_cvt, s2);

    // s3: attention coefficients
    ws_kernel<<<(HEADS * F_IN + 255) / 256, 256, 0, s3>>>(W_gat, att_s, att_d);
    asd_kernel<<<(N_NODES * HEADS + 255) / 256, 256, 0, s3>>>(x);
    cudaEventRecord(e_asd, s3);

    // main: critical converts -> GAT GEMM
    cvt_crit_kernel<<<(CVT_CRIT + 255) / 256, 256>>>(x, W_gat);
    mma_gemm<false, false, true><<<dim3(NP_GAT / 128, M_PAD / 128), 256, GEMM_SMEM>>>(
        axh, bgat, nullptr, nullptr, nullptr, xth, KP_X, KP_X / 64, D1, XTS, 0);

    cudaStreamWaitEvent(0, e_csr, 0);
    cudaStreamWaitEvent(0, e_asd, 0);

    gat_gather_kernel<<<(N_NODES * 32 + 255) / 256, 256>>>(b_gat);
    cudaEventRecord(e_h1, 0);

    cudaStreamWaitEvent(s2, e_h1, 0);

    const int N0 = MSPLIT_NODE, N1 = N_NODES - MSPLIT_NODE;

    // half 0 (default stream)
    gcn_gather_kernel<<<(N0 * 32 + 255) / 256, 256>>>(0, N0);
    cudaStreamWaitEvent(0, e_cvt, 0);
    mma_gemm<true, true, true><<<dim3(NP_GCN / 128, MBLK0), 256, GEMM_SMEM>>>(
        aah, bgcn, b_gcn, nullptr, nullptr, a2h, KP_AGG, KP_AGG / 64, D2, KP_H2, 0);
    mma_gemm<true, true, true><<<dim3(NP_G1 / 128, MBLK0), 256, GEMM_SMEM>>>(
        a2h, bg1, b_g1, nullptr, nullptr, a3h, KP_H2, KP_H2 / 64, D3, KP_H3, 0);
    mma_gemm<false, false, false><<<dim3(NP_G2 / 128, MBLK0, 2), 256, GEMM_SMEM>>>(
        a3h, bg2, nullptr, p_h4a, p_h4b, nullptr, KP_H3, KP_H3 / 128, D4, D4, 0);
    tail_kernel<<<(N0 * 32 + 255) / 256, 256>>>(
        W_fc1, b_fc1, W_fc2, b_fc2, W_out, b_out, b_g2, out, 0, N0);

    // half 1 (stream s2)
    gcn_gather_kernel<<<(N1 * 32 + 255) / 256, 256, 0, s2>>>(MSPLIT_NODE, N1);
    mma_gemm<true, true, true><<<dim3(NP_GCN / 128, MBLK1), 256, GEMM_SMEM, s2>>>(
        aah, bgcn, b_gcn, nullptr, nullptr, a2h, KP_AGG, KP_AGG / 64, D2, KP_H2, MBLK0);
    mma_gemm<true, true, true><<<dim3(NP_G1 / 128, MBLK1), 256, GEMM_SMEM, s2>>>(
        a2h, bg1, b_g1, nullptr, nullptr, a3h, KP_H2, KP_H2 / 64, D3, KP_H3, MBLK0);
    mma_gemm<false, false, false><<<dim3(NP_G2 / 128, MBLK1, 2), 256, GEMM_SMEM, s2>>>(
        a3h, bg2, nullptr, p_h4a, p_h4b, nullptr, KP_H3, KP_H3 / 128, D4, D4, MBLK0);
    tail_kernel<<<(N1 * 32 + 255) / 256, 256, 0, s2>>>(
        W_fc1, b_fc1, W_fc2, b_fc2, W_out, b_out, b_g2, out, MSPLIT_NODE, N1);
    cudaEventRecord(e_done2, s2);

    cudaStreamWaitEvent(0, e_done2, 0);

    cudaEventDestroy(e_fork);
    cudaEventDestroy(e_csr);
    cudaEventDestroy(e_asd);
    cudaEventDestroy(e_cvt);
    cudaEventDestroy(e_h1);
    cudaEventDestroy(e_done2);
    cudaStreamDestroy(s2);
    cudaStreamDestroy(s3);
}

// round 15
// speedup vs baseline: 1.4983x; 1.0211x over previous
#include <cuda_runtime.h>
#include <cuda_fp16.h>
#include <math.h>
#include <stdint.h>

#define N_NODES 10000
#define N_EDGES 120000
#define E_TOT   130000
#define F_IN    66
#define HEADS   10
#define FHEAD   66
#define D1      660
#define D2      1320
#define D3      1000
#define D4      64
#define M_PAD   10112        // 79 * 128

#define KP_X    128
#define KP_AGG  704          // cols [672,704) stay zero (static init)
#define KP_H2   1344
#define KP_H3   1024
#define NP_GAT  768
#define NP_GCN  1408
#define NP_G1   1024
#define NP_G2   128
#define XTS     672

#define MSPLIT_NODE 5120
#define MBLK0 40
#define MBLK1 39

// ---------------- scratch ------------------------------------------------------
__device__             float g_as [N_NODES * HEADS];
__device__             float g_ad [N_NODES * HEADS];
__device__             float g_ws [HEADS * F_IN];
__device__             float g_wd [HEADS * F_IN];
__device__             float g_dinv[N_NODES];
__device__ __align__(16) float g_h4a[N_NODES * D4];
__device__ __align__(16) float g_h4b[N_NODES * D4];

__device__ __align__(16) __half g_xth [N_NODES * XTS];
__device__ __align__(16) __half g_h1h [N_NODES * XTS];

// ---------------- CSR over destination ------------------------------------------
__device__ int g_deg_i [N_NODES];
__device__ int g_fill  [N_NODES];     // seeded with rowptr by scan_kernel
__device__ int g_rowptr[N_NODES + 1];
__device__ int g_csr_src[E_TOT];

// ---------------- fp16 GEMM buffers ----------------------------------------------
__device__ __align__(16) __half g_axh [M_PAD * KP_X];
__device__ __align__(16) __half g_aah [M_PAD * KP_AGG];
__device__ __align__(16) __half g_a2h [M_PAD * KP_H2];
__device__ __align__(16) __half g_a3h [M_PAD * KP_H3];
__device__ __align__(16) __half g_bgat[NP_GAT * KP_X];
__device__ __align__(16) __half g_bgcn[NP_GCN * KP_AGG];
__device__ __align__(16) __half g_bg1 [NP_G1 * KP_H2];
__device__ __align__(16) __half g_bg2 [NP_G2 * KP_H3];

// ---------------- baseline-PTX helpers -------------------------------------------
__device__ __forceinline__ uint32_t smem_u32(const void* p) {
    uint32_t a;
    asm("{ .reg .u64 t; cvta.to.shared.u64 t, %1; cvt.u32.u64 %0, t; }" : "=r"(a) : "l"(p));
    return a;
}
__device__ __forceinline__ void cp16(uint32_t dst, const void* src) {
    asm volatile("cp.async.cg.shared.global [%0], [%1], 16;" :: "r"(dst), "l"(src));
}
__device__ __forceinline__ void cp_commit() { asm volatile("cp.async.commit_group;"); }
template<int N> __device__ __forceinline__ void cp_wait() {
    asm volatile("cp.async.wait_group %0;" :: "n"(N));
}
__device__ __forceinline__ void ldsm4(uint32_t* r, uint32_t addr) {
    asm volatile("ldmatrix.sync.aligned.m8n8.x4.shared.b16 {%0,%1,%2,%3}, [%4];"
        : "=r"(r[0]), "=r"(r[1]), "=r"(r[2]), "=r"(r[3]) : "r"(addr));
}
__device__ __forceinline__ void mma_f16(float* d, const uint32_t* a, const uint32_t* b) {
    asm volatile("mma.sync.aligned.m16n8k16.row.col.f32.f16.f16.f32 "
        "{%0,%1,%2,%3}, {%4,%5,%6,%7}, {%8,%9}, {%0,%1,%2,%3};"
        : "+f"(d[0]), "+f"(d[1]), "+f"(d[2]), "+f"(d[3])
        : "r"(a[0]), "r"(a[1]), "r"(a[2]), "r"(a[3]), "r"(b[0]), "r"(b[1]));
}

// ---------------- misc ------------------------------------------------------------
__device__ __forceinline__ void edge_sd(const int* ei, int e, int& s, int& d) {
    if (e < N_EDGES) { s = ei[e]; d = ei[N_EDGES + e]; }
    else             { s = d = e - N_EDGES; }
}
__device__ __forceinline__ float leaky(float v, float sl) { return v >= 0.f ? v : sl * v; }

// ---------------- CSR build ---------------------------------------------------------
__global__ void zero_small_kernel() {
    int i = blockIdx.x * blockDim.x + threadIdx.x;
    if (i < N_NODES) g_deg_i[i] = 0;
}
__global__ void deg_kernel(const int* __restrict__ ei) {
    int e = blockIdx.x * blockDim.x + threadIdx.x;
    if (e >= E_TOT) return;
    int s, d; edge_sd(ei, e, s, d);
    atomicAdd(&g_deg_i[d], 1);
}
__global__ void scan_kernel() {   // rowptr + dinv + seed fill cursors
    __shared__ int sm[1024];
    int tid = threadIdx.x;
    int base = tid * 10;
    int local[10]; int sum = 0;
    #pragma unroll
    for (int i = 0; i < 10; i++) {
        int v = (base + i < N_NODES) ? g_deg_i[base + i] : 0;
        if (base + i < N_NODES) g_dinv[base + i] = rsqrtf(fmaxf((float)v, 1.f));
        local[i] = sum; sum += v;
    }
    sm[tid] = sum; __syncthreads();
    for (int off = 1; off < 1024; off <<= 1) {
        int v = (tid >= off) ? sm[tid - off] : 0;
        __syncthreads();
        sm[tid] += v;
        __syncthreads();
    }
    int pre = (tid > 0) ? sm[tid - 1] : 0;
    #pragma unroll
    for (int i = 0; i < 10; i++)
        if (base + i < N_NODES) {
            int rp = pre + local[i];
            g_rowptr[base + i] = rp;
            g_fill[base + i] = rp;     // absolute cursor
        }
    if (tid == 1023) g_rowptr[N_NODES] = sm[1023];
}
__global__ void fill_kernel(const int* __restrict__ ei) {
    int e = blockIdx.x * blockDim.x + threadIdx.x;
    if (e >= E_TOT) return;
    int s, d; edge_sd(ei, e, s, d);
    int pos = atomicAdd(&g_fill[d], 1);
    g_csr_src[pos] = s;
}

// ---------------- attn hoist --------------------------------------------------------
__global__ void ws_kernel(const float* __restrict__ Wgat,
                          const float* __restrict__ att_s, const float* __restrict__ att_d) {
    int idx = blockIdx.x * blockDim.x + threadIdx.x;
    if (idx >= HEADS * F_IN) return;
    int h = idx / F_IN, i = idx - h * F_IN;
    const float* wrow = Wgat + (long)i * D1 + h * FHEAD;
    const float* as = att_s + h * FHEAD;
    const float* ad = att_d + h * FHEAD;
    float s = 0.f, d = 0.f;
    #pragma unroll
    for (int f = 0; f < FHEAD; f++) { float w = wrow[f]; s += w * as[f]; d += w * ad[f]; }
    g_ws[idx] = s; g_wd[idx] = d;
}
__global__ void asd_kernel(const float* __restrict__ x) {
    int idx = blockIdx.x * blockDim.x + threadIdx.x;
    if (idx >= N_NODES * HEADS) return;
    int n = idx / HEADS, h = idx - n * HEADS;
    const float* xr = x + (long)n * F_IN;
    const float* ws = g_ws + h * F_IN;
    const float* wd = g_wd + h * F_IN;
    float s = 0.f, d = 0.f;
    #pragma unroll
    for (int i = 0; i < F_IN; i++) { float v = xr[i]; s += v * ws[i]; d += v * wd[i]; }
    g_as[idx] = s; g_ad[idx] = d;
}

// ---------------- converts ------------------------------------------------------------
#define R0 (NP_GAT * KP_X)
#define R4 (M_PAD * KP_X)
#define CVT_CRIT (R0 + R4)
#define R1 (NP_GCN * KP_AGG)
#define R2 (NP_G1 * KP_H2)
#define R3 (NP_G2 * KP_H3)
#define CVT_REST (R1 + R2 + R3)

__device__ __forceinline__ void cvtB_one(const float* W, __half* dst, int idx,
                                         int K, int Nn, int Kp) {
    int n = idx / Kp, k = idx - n * Kp;
    float v = (k < K && n < Nn) ? W[(long)k * Nn + n] : 0.f;
    dst[idx] = __float2half_rn(v);
}
__global__ void cvt_crit_kernel(const float* __restrict__ x, const float* __restrict__ Wgat) {
    int idx = blockIdx.x * blockDim.x + threadIdx.x;
    if (idx >= CVT_CRIT) return;
    if (idx < R0) { cvtB_one(Wgat, g_bgat, idx, F_IN, D1, KP_X); return; }
    idx -= R0;
    int r = idx / KP_X, c = idx - r * KP_X;
    float v = (r < N_NODES && c < F_IN) ? x[(long)r * F_IN + c] : 0.f;
    g_axh[idx] = __float2half_rn(v);
}
__global__ void cvt_rest_kernel(const float* __restrict__ Wgcn,
                                const float* __restrict__ Wg1, const float* __restrict__ Wg2) {
    int idx = blockIdx.x * blockDim.x + threadIdx.x;
    if (idx >= CVT_REST) return;
    if (idx < R1) { cvtB_one(Wgcn, g_bgcn, idx, D1, D2, KP_AGG); return; }
    idx -= R1;
    if (idx < R2) { cvtB_one(Wg1, g_bg1, idx, D2, D3, KP_H2); return; }
    idx -= R2;
    cvtB_one(Wg2, g_bg2, idx, D3, D4, KP_H3);
}

// ---------------- HMMA GEMM: BK=64, 3-stage cp.async, 2 CTAs/SM -----------------------
#define TSTRIDE  144
#define B_HI_OFF 18432
#define STAGE_SZ 36864
#define GEMM_SMEM (3 * STAGE_SZ)

__device__ __forceinline__ void fill_stage(uint32_t st,
        const __half* __restrict__ A, const __half* __restrict__ B,
        int m0, int n0, int Kp, int k0, int tid) {
    #pragma unroll
    for (int i = 0; i < 4; i++) {
        int lin = tid + i * 256;
        int r = lin >> 3, cc = lin & 7;
        uint32_t d = st + r * TSTRIDE + cc * 16;
        cp16(d,            (const char*)(A + (long)(m0 + r) * Kp + k0) + cc * 16);
        cp16(d + B_HI_OFF, (const char*)(B + (long)(n0 + r) * Kp + k0) + cc * 16);
    }
    cp_commit();
}

template<bool BIAS, bool ACT, bool SPLIT>
__global__ __launch_bounds__(256, 2)
void mma_gemm(const __half* __restrict__ Ah, const __half* __restrict__ Bh,
              const float* __restrict__ bias, float* __restrict__ C,
              float* __restrict__ C2, __half* __restrict__ Sh,
              int Kp, int chunks, int Nreal, int ldC, int mblk_off) {
    extern __shared__ char smem[];
    const uint32_t tile0 = smem_u32(smem);
    const int tid = threadIdx.x, wid = tid >> 5, lane = tid & 31;
    const int m0 = (blockIdx.y + mblk_off) * 128, n0 = blockIdx.x * 128;
    const int kbase = blockIdx.z * chunks * 64;
    const int mwoff = (wid >> 1) * 32, nwoff = (wid & 1) * 64;

    const int mat = lane >> 3, mrow = lane & 7;
    uint32_t a_off[2], b_off[4];
    #pragma unroll
    for (int ti = 0; ti < 2; ti++)
        a_off[ti] = (uint32_t)((mwoff + ti * 16 + ((mat & 1) << 3) + mrow) * TSTRIDE
                               + (mat >> 1) * 16);
    #pragma unroll
    for (int nt = 0; nt < 4; nt++)
        b_off[nt] = (uint32_t)((nwoff + nt * 16 + ((mat >> 1) << 3) + mrow) * TSTRIDE
                               + (mat & 1) * 16);

    float acc[2][8][4] = {};

    fill_stage(tile0, Ah, Bh, m0, n0, Kp, kbase, tid);
    if (chunks > 1) fill_stage(tile0 + STAGE_SZ, Ah, Bh, m0, n0, Kp, kbase + 64, tid);

    int sidx = 0;
    for (int c = 0; c < chunks; c++) {
        if (c + 1 < chunks) cp_wait<1>(); else cp_wait<0>();
        __syncthreads();
        if (c + 2 < chunks) {
            int nxt = sidx + 2; if (nxt >= 3) nxt -= 3;
            fill_stage(tile0 + nxt * STAGE_SZ, Ah, Bh, m0, n0, Kp, kbase + (c + 2) * 64, tid);
        }
        uint32_t sb = tile0 + sidx * STAGE_SZ;
        #pragma unroll
        for (int kh = 0; kh < 4; kh++) {
            uint32_t ah[2][4], bh[4][4];
            #pragma unroll
            for (int ti = 0; ti < 2; ti++)
                ldsm4(ah[ti], sb + a_off[ti] + kh * 32);
            #pragma unroll
            for (int nt = 0; nt < 4; nt++)
                ldsm4(bh[nt], sb + B_HI_OFF + b_off[nt] + kh * 32);
            #pragma unroll
            for (int ti = 0; ti < 2; ti++)
                #pragma unroll
                for (int nt = 0; nt < 8; nt++)
                    mma_f16(acc[ti][nt], ah[ti], &bh[nt >> 1][(nt & 1) * 2]);
        }
        if (++sidx >= 3) sidx = 0;
    }

    float* Cout = (blockIdx.z == 0) ? C : C2;
    const int lr = lane >> 2, lc = (lane & 3) * 2;
    #pragma unroll
    for (int ti = 0; ti < 2; ti++)
        #pragma unroll
        for (int rp = 0; rp < 2; rp++) {
            int gr = m0 + mwoff + ti * 16 + rp * 8 + lr;
            if (gr >= N_NODES) continue;
            if (!SPLIT) {
                float* crow = Cout + (long)gr * ldC;
                #pragma unroll
                for (int nt = 0; nt < 8; nt++) {
                    int gc = n0 + nwoff + nt * 8 + lc;
                    float v0 = acc[ti][nt][rp * 2 + 0];
                    float v1 = acc[ti][nt][rp * 2 + 1];
                    if (gc < Nreal) {
                        if (BIAS) v0 += bias[gc];
                        if (ACT)  v0 = leaky(v0, 0.01f);
                        crow[gc] = v0;
                    }
                    if (gc + 1 < Nreal) {
                        if (BIAS) v1 += bias[gc + 1];
                        if (ACT)  v1 = leaky(v1, 0.01f);
                        crow[gc + 1] = v1;
                    }
                }
            } else {
                __half* hr = Sh + (long)gr * ldC;
                #pragma unroll
                for (int nt = 0; nt < 8; nt++) {
                    int gc = n0 + nwoff + nt * 8 + lc;
                    if (gc >= ldC) continue;
                    float v0 = 0.f, v1 = 0.f;
                    if (gc < Nreal) {
                        v0 = acc[ti][nt][rp * 2 + 0];
                        if (BIAS) v0 += bias[gc];
                        if (ACT)  v0 = leaky(v0, 0.01f);
                    }
                    if (gc + 1 < Nreal) {
                        v1 = acc[ti][nt][rp * 2 + 1];
                        if (BIAS) v1 += bias[gc + 1];
                        if (ACT)  v1 = leaky(v1, 0.01f);
                    }
                    __half2 hp;
                    hp.x = __float2half_rn(v0);
                    hp.y = __float2half_rn(v1);
                    *(__half2*)(hr + gc) = hp;
                }
            }
        }
}

// ---------------- GAT gather: single pass, warp-uniform shuffle broadcast --------
__global__ void gat_gather_kernel(const float* __restrict__ b_gat) {
    int gw = (blockIdx.x * blockDim.x + threadIdx.x) >> 5;
    int lane = threadIdx.x & 31;
    if (gw >= N_NODES) return;
    int beg = g_rowptr[gw], end = g_rowptr[gw + 1];

    float adl = (lane < HEADS) ? g_ad[gw * HEADS + lane] : 0.f;

    int h0[3], pos[3], valid[3];
    #pragma unroll
    for (int j = 0; j < 3; j++) {
        int f4 = lane + 32 * j;
        valid[j] = (f4 < XTS / 8);
        int f0 = f4 * 8;
        int hh = f0 / FHEAD; if (hh > 9) hh = 9;
        h0[j] = hh;
        pos[j] = (hh + 1) * FHEAD - f0;
    }

    float acc[3][8] = {};
    float ssum = 0.f;

    for (int i = beg; i < end; i++) {
        int src = g_csr_src[i];
        float w = (lane < HEADS)
            ? expf(leaky(g_as[src * HEADS + lane] + adl, 0.2f)) : 0.f;
        ssum += w;
        // shuffles are warp-uniform (ALL lanes execute every shfl; h0 defined
        // for every lane). Lane >= HEADS holds w=0, so h0+1==10 reads 0.
        float s0[3], s1[3];
        #pragma unroll
        for (int j = 0; j < 3; j++) {
            s0[j] = __shfl_sync(0xffffffffu, w, h0[j]);
            s1[j] = __shfl_sync(0xffffffffu, w, h0[j] + 1);
        }
        const float4* xs = (const float4*)(g_xth + (long)src * XTS);
        #pragma unroll
        for (int j = 0; j < 3; j++) {
            if (!valid[j]) continue;
            float4 raw = xs[lane + 32 * j];
            const __half2* hp = (const __half2*)&raw;
            #pragma unroll
            for (int k = 0; k < 4; k++) {
                float2 v = __half22float2(hp[k]);
                acc[j][2 * k + 0] += v.x * (2 * k     < pos[j] ? s0[j] : s1[j]);
                acc[j][2 * k + 1] += v.y * (2 * k + 1 < pos[j] ? s0[j] : s1[j]);
            }
        }
    }

    float inv = (lane < HEADS) ? 1.f / fmaxf(ssum, 1e-16f) : 0.f;
    float i0[3], i1[3];
    #pragma unroll
    for (int j = 0; j < 3; j++) {       // warp-uniform
        i0[j] = __shfl_sync(0xffffffffu, inv, h0[j]);
        i1[j] = __shfl_sync(0xffffffffu, inv, h0[j] + 1);
    }

    __half* hd = g_h1h + (long)gw * XTS;
    #pragma unroll
    for (int j = 0; j < 3; j++) {
        if (!valid[j]) continue;
        int f0 = (lane + 32 * j) * 8;
        __half2 o[4];
        #pragma unroll
        for (int k = 0; k < 8; k++) {
            int f = f0 + k;
            float iv = (k < pos[j]) ? i0[j] : i1[j];
            float v = (f < D1) ? leaky(acc[j][k] * iv + b_gat[f], 0.01f) : 0.f;
            ((__half*)o)[k] = __float2half_rn(v);
        }
        *(float4*)(hd + f0) = *(float4*)o;
    }
}

// ---------------- GCN gather over node range ---------------------------------------
__global__ void gcn_gather_kernel(int node0, int ncount) {
    int gw = node0 + ((blockIdx.x * blockDim.x + threadIdx.x) >> 5);
    int lane = threadIdx.x & 31;
    if (gw >= node0 + ncount || gw >= N_NODES) return;
    int beg = g_rowptr[gw], end = g_rowptr[gw + 1];
    float dd = g_dinv[gw];

    float acc[3][8] = {};
    int valid[3];
    #pragma unroll
    for (int j = 0; j < 3; j++) valid[j] = (lane + 32 * j) < XTS / 8;

    for (int i = beg; i < end; i++) {
        int src = g_csr_src[i];
        float nm = dd * g_dinv[src];
        const float4* hs = (const float4*)(g_h1h + (long)src * XTS);
        #pragma unroll
        for (int j = 0; j < 3; j++) {
            if (!valid[j]) continue;
            float4 raw = hs[lane + 32 * j];
            const __half2* hp = (const __half2*)&raw;
            #pragma unroll
            for (int k = 0; k < 4; k++) {
                float2 v = __half22float2(hp[k]);
                acc[j][2 * k + 0] += v.x * nm;
                acc[j][2 * k + 1] += v.y * nm;
            }
        }
    }

    __half* hr = g_aah + (long)gw * KP_AGG;
    #pragma unroll
    for (int j = 0; j < 3; j++) {
        if (!valid[j]) continue;
        int f0 = (lane + 32 * j) * 8;
        __half2 o[4];
        #pragma unroll
        for (int k = 0; k < 8; k++)
            ((__half*)o)[k] = __float2half_rn(acc[j][k]);
        *(float4*)(hr + f0) = *(float4*)o;
    }
}

// ---------------- tail over node range ----------------------------------------------
__global__ void tail_kernel(const float* __restrict__ W1, const float* __restrict__ b1,
                            const float* __restrict__ W2, const float* __restrict__ b2,
                            const float* __restrict__ W3, const float* __restrict__ b3,
                            const float* __restrict__ bg2,
                            float* __restrict__ out, int node0, int ncount) {
    int gw = node0 + ((blockIdx.x * blockDim.x + threadIdx.x) >> 5);
    int lane = threadIdx.x & 31;
    if (gw >= node0 + ncount || gw >= N_NODES) return;
    float v0 = leaky(g_h4a[gw * 64 + lane] + g_h4b[gw * 64 + lane] + bg2[lane], 0.01f);
    float v1 = leaky(g_h4a[gw * 64 + 32 + lane] + g_h4b[gw * 64 + 32 + lane] + bg2[32 + lane], 0.01f);
    float s = b1[lane];
    #pragma unroll
    for (int k = 0; k < 32; k++) s += __shfl_sync(0xffffffffu, v0, k) * W1[k * 32 + lane];
    #pragma unroll
    for (int k = 0; k < 32; k++) s += __shfl_sync(0xffffffffu, v1, k) * W1[(k + 32) * 32 + lane];
    float u = leaky(s, 0.01f);
    int j = lane & 15;
    float s2 = b2[j];
    #pragma unroll
    for (int k = 0; k < 32; k++) s2 += __shfl_sync(0xffffffffu, u, k) * W2[k * 16 + j];
    float t = leaky(s2, 0.01f);
    float o = (lane < 16) ? t * W3[lane] : 0.f;
    #pragma unroll
    for (int off = 8; off > 0; off >>= 1) o += __shfl_down_sync(0xffffffffu, o, off);
    if (lane == 0) out[gw] = o + b3[0];
}

// ---------------- launch --------------------------------------------------------------
extern "C" void kernel_launch(void* const* d_in, const int* in_sizes, int n_in,
                              void* d_out, int out_size) {
    const float* x     = (const float*)d_in[0];
    const int*   ei    = (const int*)  d_in[1];
    const float* W_gat = (const float*)d_in[2];
    const float* att_s = (const float*)d_in[3];
    const float* att_d = (const float*)d_in[4];
    const float* b_gat = (const float*)d_in[5];
    const float* W_gcn = (const float*)d_in[6];
    const float* b_gcn = (const float*)d_in[7];
    const float* W_g1  = (const float*)d_in[8];
    const float* b_g1  = (const float*)d_in[9];
    const float* W_g2  = (const float*)d_in[10];
    const float* b_g2  = (const float*)d_in[11];
    const float* W_fc1 = (const float*)d_in[12];
    const float* b_fc1 = (const float*)d_in[13];
    const float* W_fc2 = (const float*)d_in[14];
    const float* b_fc2 = (const float*)d_in[15];
    const float* W_out = (const float*)d_in[16];
    const float* b_out = (const float*)d_in[17];
    float* out = (float*)d_out;
    (void)in_sizes; (void)n_in; (void)out_size;

    cudaFuncSetAttribute(mma_gemm<false, false, true>, cudaFuncAttributeMaxDynamicSharedMemorySize, GEMM_SMEM);
    cudaFuncSetAttribute(mma_gemm<true, true, true>,   cudaFuncAttributeMaxDynamicSharedMemorySize, GEMM_SMEM);
    cudaFuncSetAttribute(mma_gemm<false, false, false>, cudaFuncAttributeMaxDynamicSharedMemorySize, GEMM_SMEM);

    float *p_h4a, *p_h4b;
    cudaGetSymbolAddress((void**)&p_h4a, g_h4a);
    cudaGetSymbolAddress((void**)&p_h4b, g_h4b);
    #define HADDR(p, s) __half* p; cudaGetSymbolAddress((void**)&p, s)
    HADDR(axh, g_axh); HADDR(aah, g_aah);
    HADDR(a2h, g_a2h); HADDR(a3h, g_a3h);
    HADDR(bgat, g_bgat); HADDR(bgcn, g_bgcn);
    HADDR(bg1, g_bg1); HADDR(bg2, g_bg2);
    HADDR(xth, g_xth);

    cudaStream_t s2, s3;
    cudaStreamCreateWithFlags(&s2, cudaStreamNonBlocking);
    cudaStreamCreateWithFlags(&s3, cudaStreamNonBlocking);
    cudaEvent_t e_fork, e_csr, e_asd, e_cvt, e_h1, e_done2;
    cudaEventCreateWithFlags(&e_fork, cudaEventDisableTiming);
    cudaEventCreateWithFlags(&e_csr,  cudaEventDisableTiming);
    cudaEventCreateWithFlags(&e_asd,  cudaEventDisableTiming);
    cudaEventCreateWithFlags(&e_cvt,  cudaEventDisableTiming);
    cudaEventCreateWithFlags(&e_h1,   cudaEventDisableTiming);
    cudaEventCreateWithFlags(&e_done2, cudaEventDisableTiming);

    cudaEventRecord(e_fork, 0);
    cudaStreamWaitEvent(s2, e_fork, 0);
    cudaStreamWaitEvent(s3, e_fork, 0);

    // s2: CSR chain, then non-critical converts
    zero_small_kernel<<<(N_NODES + 255) / 256, 256, 0, s2>>>();
    deg_kernel<<<(E_TOT + 255) / 256, 256, 0, s2>>>(ei);
    scan_kernel<<<1, 1024, 0, s2>>>();
    fill_kernel<<<(E_TOT + 255) / 256, 256, 0, s2>>>(ei);
    cudaEventRecord(e_csr, s2);
    cvt_rest_kernel<<<(CVT_REST + 255) / 256, 256, 0, s2>>>(W_gcn, W_g1, W_g2);
    cudaEventRecord(e_cvt, s2);

    // s3: attention coefficients
    ws_kernel<<<(HEADS * F_IN + 255) / 256, 256, 0, s3>>>(W_gat, att_s, att_d);
    asd_kernel<<<(N_NODES * HEADS + 255) / 256, 256, 0, s3>>>(x);
    cudaEventRecord(e_asd, s3);

    // main: critical converts -> GAT GEMM
    cvt_crit_kernel<<<(CVT_CRIT + 255) / 256, 256>>>(x, W_gat);
    mma_gemm<false, false, true><<<dim3(NP_GAT / 128, M_PAD / 128), 256, GEMM_SMEM>>>(
        axh, bgat, nullptr, nullptr, nullptr, xth, KP_X, KP_X / 64, D1, XTS, 0);

    cudaStreamWaitEvent(0, e_csr, 0);
    cudaStreamWaitEvent(0, e_asd, 0);

    gat_gather_kernel<<<(N_NODES * 32 + 255) / 256, 256>>>(b_gat);
    cudaEventRecord(e_h1, 0);

    cudaStreamWaitEvent(s2, e_h1, 0);

    const int N0 = MSPLIT_NODE, N1 = N_NODES - MSPLIT_NODE;

    // half 0 (default stream)
    gcn_gather_kernel<<<(N0 * 32 + 255) / 256, 256>>>(0, N0);
    cudaStreamWaitEvent(0, e_cvt, 0);
    mma_gemm<true, true, true><<<dim3(NP_GCN / 128, MBLK0), 256, GEMM_SMEM>>>(
        aah, bgcn, b_gcn, nullptr, nullptr, a2h, KP_AGG, KP_AGG / 64, D2, KP_H2, 0);
    mma_gemm<true, true, true><<<dim3(NP_G1 / 128, MBLK0), 256, GEMM_SMEM>>>(
        a2h, bg1, b_g1, nullptr, nullptr, a3h, KP_H2, KP_H2 / 64, D3, KP_H3, 0);
    mma_gemm<false, false, false><<<dim3(NP_G2 / 128, MBLK0, 2), 256, GEMM_SMEM>>>(
        a3h, bg2, nullptr, p_h4a, p_h4b, nullptr, KP_H3, KP_H3 / 128, D4, D4, 0);
    tail_kernel<<<(N0 * 32 + 255) / 256, 256>>>(
        W_fc1, b_fc1, W_fc2, b_fc2, W_out, b_out, b_g2, out, 0, N0);

    // half 1 (stream s2)
    gcn_gather_kernel<<<(N1 * 32 + 255) / 256, 256, 0, s2>>>(MSPLIT_NODE, N1);
    mma_gemm<true, true, true><<<dim3(NP_GCN / 128, MBLK1), 256, GEMM_SMEM, s2>>>(
        aah, bgcn, b_gcn, nullptr, nullptr, a2h, KP_AGG, KP_AGG / 64, D2, KP_H2, MBLK0);
    mma_gemm<true, true, true><<<dim3(NP_G1 / 128, MBLK1), 256, GEMM_SMEM, s2>>>(
        a2h, bg1, b_g1, nullptr, nullptr, a3h, KP_H2, KP_H2 / 64, D3, KP_H3, MBLK0);
    mma_gemm<false, false, false><<<dim3(NP_G2 / 128, MBLK1, 2), 256, GEMM_SMEM, s2>>>(
        a3h, bg2, nullptr, p_h4a, p_h4b, nullptr, KP_H3, KP_H3 / 128, D4, D4, MBLK0);
    tail_kernel<<<(N1 * 32 + 255) / 256, 256, 0, s2>>>(
        W_fc1, b_fc1, W_fc2, b_fc2, W_out, b_out, b_g2, out, MSPLIT_NODE, N1);
    cudaEventRecord(e_done2, s2);

    cudaStreamWaitEvent(0, e_done2, 0);

    cudaEventDestroy(e_fork);
    cudaEventDestroy(e_csr);
    cudaEventDestroy(e_asd);
    cudaEventDestroy(e_cvt);
    cudaEventDestroy(e_h1);
    cudaEventDestroy(e_done2);
    cudaStreamDestroy(s2);
    cudaStreamDestroy(s3);
}